// round 9
// baseline (speedup 1.0000x reference)
#include <cuda_runtime.h>
#include <cuda_bf16.h>
#include <math.h>
#include <stdint.h>

// ---- problem constants ----
#define Bsz 4096
#define Lm  30
#define Wm  5
#define Am  30
#define Em  128
#define Cch 40
#define Hm  128
#define Tm  3
#define LIN 200
#define FK  208          // valid K
#define KPS 256          // padded K stride for bf16 planes
#define Nt  (Bsz*Lm)     // 122880 tokens
#define G4  512          // 4*H gates
#define NCH 13           // 208/16 k-chunks

typedef unsigned long long u64;

// ---- packed f32x2 helpers (FFMA2 path) ----
__device__ __forceinline__ u64 pack2(float lo, float hi) {
    u64 r; asm("mov.b64 %0,{%1,%2};" : "=l"(r) : "f"(lo), "f"(hi)); return r;
}
__device__ __forceinline__ u64 splat2(float v) { return pack2(v, v); }
__device__ __forceinline__ u64 fma2(u64 a, u64 b, u64 c) {
    u64 d; asm("fma.rn.f32x2 %0,%1,%2,%3;" : "=l"(d) : "l"(a), "l"(b), "l"(c)); return d;
}
__device__ __forceinline__ void unpack2(u64 v, float& lo, float& hi) {
    asm("mov.b64 {%0,%1},%2;" : "=f"(lo), "=f"(hi) : "l"(v));
}
__device__ __forceinline__ float sigf(float x) {
    return __fdividef(1.f, 1.f + __expf(-x));
}
__device__ __forceinline__ float tanhfast(float x) {
    return __fdividef(2.f, 1.f + __expf(-2.f * x)) - 1.f;
}
__device__ __forceinline__ void cpasync16(uint32_t smem, const void* gmem) {
    asm volatile("cp.async.ca.shared.global [%0],[%1],16;" :: "r"(smem), "l"(gmem));
}
__device__ __forceinline__ void cpcommit() {
    asm volatile("cp.async.commit_group;");
}
__device__ __forceinline__ uint32_t smem_u32(const void* p) {
    uint32_t a;
    asm("{ .reg .u64 t; cvta.to.shared.u64 t, %1; cvt.u32.u64 %0, t; }" : "=r"(a) : "l"(p));
    return a;
}
__device__ __forceinline__ void split3(float v, __nv_bfloat16& h, __nv_bfloat16& m, __nv_bfloat16& l) {
    h = __float2bfloat16(v);
    float r = v - __bfloat162float(h);
    m = __float2bfloat16(r);
    r -= __bfloat162float(m);
    l = __float2bfloat16(r);
}
#define LDSM4(d, addr) \
    asm volatile("ldmatrix.sync.aligned.m8n8.x4.shared.b16 {%0,%1,%2,%3},[%4];" \
        : "=r"((d)[0]), "=r"((d)[1]), "=r"((d)[2]), "=r"((d)[3]) : "r"(addr))
__device__ __forceinline__ void mma_bf16(float* d, const uint32_t* a, uint32_t b0, uint32_t b1) {
    asm volatile(
        "mma.sync.aligned.m16n8k16.row.col.f32.bf16.bf16.f32 "
        "{%0,%1,%2,%3},{%4,%5,%6,%7},{%8,%9},{%0,%1,%2,%3};"
        : "+f"(d[0]), "+f"(d[1]), "+f"(d[2]), "+f"(d[3])
        : "r"(a[0]), "r"(a[1]), "r"(a[2]), "r"(a[3]), "r"(b0), "r"(b1));
}

// ---- device scratch ----
__device__ float g_M[Am*Cch*3];
__device__ float g_bias1[Cch];
__device__ __align__(128) __nv_bfloat16 g_wB[2*3*(size_t)G4*KPS];   // [dir*3+plane][g][k]
__device__ float g_whhT[2][Hm*G4];
__device__ float g_fcf[Tm*Hm];
__device__ float g_fcb[Tm*Hm];
__device__ float g_cbias[Tm];
__device__ float g_featT[(size_t)FK*Nt];                              // k-major fp32 staging
__device__ __align__(128) __nv_bfloat16 g_featB[3*(size_t)Nt*KPS];   // [plane][n][k]
__device__ float g_gates[2][(size_t)Nt*G4];
__device__ float g_h[2][(size_t)Nt*Hm];
__device__ float g_emis[(size_t)Nt*Tm];

// ======================= prep kernels =======================
__global__ void prep_tables(const float* __restrict__ emb,
                            const float* __restrict__ conv_w,
                            const float* __restrict__ conv_b,
                            const float* __restrict__ g1,
                            const float* __restrict__ b1,
                            const float* __restrict__ m1,
                            const float* __restrict__ v1)
{
    int i = blockIdx.x*blockDim.x + threadIdx.x;
    if (i < Am*Cch*3) {
        int k = i % 3;
        int c = (i/3) % Cch;
        int a = i / (3*Cch);
        float s = 0.f;
        for (int e = 0; e < Em; e++)
            s += emb[a*Em + e] * conv_w[(c*Em + e)*3 + k];
        float sc = g1[c] * rsqrtf(v1[c] + 1e-5f);
        g_M[i] = s * sc;
    } else if (i < Am*Cch*3 + Cch) {
        int c = i - Am*Cch*3;
        float sc = g1[c] * rsqrtf(v1[c] + 1e-5f);
        g_bias1[c] = (conv_b[c] - m1[c]) * sc + b1[c];
    }
}

__global__ void prep_pack5(const float* __restrict__ wihf, const float* __restrict__ whhf,
                           const float* __restrict__ wihb, const float* __restrict__ whhb)
{
    int stride = gridDim.x * blockDim.x;
    int t0 = blockIdx.x*blockDim.x + threadIdx.x;
    for (int i = t0; i < G4*KPS; i += stride) {
        int g = i / KPS, k = i % KPS;
        float vf = (k < LIN) ? wihf[g*LIN + k] : 0.f;
        float vb = (k < LIN) ? wihb[g*LIN + k] : 0.f;
        __nv_bfloat16 h, m, l;
        split3(vf, h, m, l);
        g_wB[(size_t)(0*3+0)*G4*KPS + i] = h;
        g_wB[(size_t)(0*3+1)*G4*KPS + i] = m;
        g_wB[(size_t)(0*3+2)*G4*KPS + i] = l;
        split3(vb, h, m, l);
        g_wB[(size_t)(1*3+0)*G4*KPS + i] = h;
        g_wB[(size_t)(1*3+1)*G4*KPS + i] = m;
        g_wB[(size_t)(1*3+2)*G4*KPS + i] = l;
    }
    for (int i = t0; i < Hm*G4; i += stride) {
        int k = i / G4, g = i % G4;
        g_whhT[0][i] = whhf[g*Hm + k];
        g_whhT[1][i] = whhb[g*Hm + k];
    }
}

__global__ void prep_fc(const float* __restrict__ g2, const float* __restrict__ b2,
                        const float* __restrict__ m2, const float* __restrict__ v2,
                        const float* __restrict__ fcw, const float* __restrict__ fcbias)
{
    int t = threadIdx.x;
    if (t < Hm) {
        float s2a = g2[t]       * rsqrtf(v2[t]       + 1e-5f);
        float s2b = g2[Hm + t]  * rsqrtf(v2[Hm + t]  + 1e-5f);
        for (int tt = 0; tt < Tm; tt++) {
            g_fcf[tt*Hm + t] = fcw[tt*2*Hm + t]      * s2a;
            g_fcb[tt*Hm + t] = fcw[tt*2*Hm + Hm + t] * s2b;
        }
    }
    if (t < Tm) {
        float s = fcbias[t];
        for (int j = 0; j < 2*Hm; j++) {
            float s2 = g2[j] * rsqrtf(v2[j] + 1e-5f);
            s += (b2[j] - m2[j]*s2) * fcw[t*2*Hm + j];
        }
        g_cbias[t] = s;
    }
}

// ======================= featurize (conv+bn+relu+pool), k-major fp32 =======================
__global__ void featurizeT(const int* __restrict__ x)
{
    int n = blockIdx.x*blockDim.x + threadIdx.x;
    int c = blockIdx.y;
    if (n >= Nt) return;
    int sym[Wm];
#pragma unroll
    for (int w = 0; w < Wm; w++) sym[w] = x[n*Wm + w];
    float y[Wm];
    float bb = g_bias1[c];
#pragma unroll
    for (int w = 0; w < Wm; w++) {
        float v = bb;
#pragma unroll
        for (int k = 0; k < 3; k++) {
            int p = w + k - 1;
            if (p >= 0 && p < Wm)
                v += g_M[sym[p]*(Cch*3) + c*3 + k];
        }
        y[w] = fmaxf(v, 0.f);
    }
#pragma unroll
    for (int w = 0; w < Wm; w++) {
        float p = y[w];
        if (w > 0)      p = fmaxf(p, y[w-1]);
        if (w < Wm-1)   p = fmaxf(p, y[w+1]);
        g_featT[(size_t)(c*Wm + w)*Nt + n] = p;
    }
    if (c == 0) {
#pragma unroll
        for (int k = LIN; k < FK; k++)
            g_featT[(size_t)k*Nt + n] = 0.f;
    }
}

// ======================= transpose + bf16 3-split: [k][n] f32 -> [plane][n][k] bf16 =======================
__global__ __launch_bounds__(256) void split_planes()
{
    __shared__ float tile[64][65];
    int tn0 = blockIdx.x * 64;
    int tk0 = blockIdx.y * 64;
    int t = threadIdx.x;
#pragma unroll
    for (int i = 0; i < 16; i++) {
        int idx = t + i*256;
        int kk = idx >> 6, nn = idx & 63;
        float v = (tk0 + kk < FK) ? g_featT[(size_t)(tk0 + kk)*Nt + tn0 + nn] : 0.f;
        tile[kk][nn] = v;
    }
    __syncthreads();
    int n  = t >> 2;
    int kg = t & 3;
    uint32_t wh[8], wm_[8], wl[8];
#pragma unroll
    for (int j = 0; j < 8; j++) {
        __nv_bfloat16 h0, m0, l0, h1, m1, l1;
        split3(tile[kg*16 + 2*j][n],     h0, m0, l0);
        split3(tile[kg*16 + 2*j + 1][n], h1, m1, l1);
        wh[j]  = (uint32_t)__bfloat16_as_ushort(h0) | ((uint32_t)__bfloat16_as_ushort(h1) << 16);
        wm_[j] = (uint32_t)__bfloat16_as_ushort(m0) | ((uint32_t)__bfloat16_as_ushort(m1) << 16);
        wl[j]  = (uint32_t)__bfloat16_as_ushort(l0) | ((uint32_t)__bfloat16_as_ushort(l1) << 16);
    }
    size_t ob = (size_t)(tn0 + n)*KPS + tk0 + kg*16;
    uint4* d0 = (uint4*)(g_featB + ob);
    uint4* d1 = (uint4*)(g_featB + (size_t)Nt*KPS + ob);
    uint4* d2 = (uint4*)(g_featB + 2*(size_t)Nt*KPS + ob);
    d0[0] = make_uint4(wh[0], wh[1], wh[2], wh[3]);
    d0[1] = make_uint4(wh[4], wh[5], wh[6], wh[7]);
    d1[0] = make_uint4(wm_[0], wm_[1], wm_[2], wm_[3]);
    d1[1] = make_uint4(wm_[4], wm_[5], wm_[6], wm_[7]);
    d2[0] = make_uint4(wl[0], wl[1], wl[2], wl[3]);
    d2[1] = make_uint4(wl[4], wl[5], wl[6], wl[7]);
}

// ======================= input GEMM v8: bf16 3-plane split, mma.m16n8k16 + ldmatrix =======================
// 128x128 block, 8 warps (wm=w&3 -> 32 M rows, wn=w>>2 -> 64 N cols).
// 6 split terms: (pb,pa): pb=h:{h,m,l}, pb=m:{h,m}, pb=l:{h}.
// Smem: 2 buf x 3 planes x (A 128x16 + B 128x16) bf16 = 48KB static.
// Row stride 32B; XOR swizzle: half ^= (row>>2)&1 -> conflict-free LDSM + cp.async.
__global__ __launch_bounds__(256, 2) void gemm_bf16s(const float* __restrict__ bias_f,
                                                     const float* __restrict__ bias_b)
{
    __shared__ __align__(16) __nv_bfloat16 As[2][3][128][16];
    __shared__ __align__(16) __nv_bfloat16 Bs[2][3][128][16];

    int dir = blockIdx.x >> 2;
    int n0  = (blockIdx.x & 3) * 128;
    int m0  = blockIdx.y * 128;
    const float* __restrict__ bias = dir ? bias_b : bias_f;
    float* __restrict__ Co = g_gates[dir];

    int t = threadIdx.x, lane = t & 31, w = t >> 5;
    int wm = w & 3, wn = w >> 2;
    int gi = lane >> 2, li = lane & 3;

    uint32_t aB[2][3], bB[2][3];
#pragma unroll
    for (int b = 0; b < 2; b++)
#pragma unroll
        for (int p = 0; p < 3; p++) {
            aB[b][p] = smem_u32(&As[b][p][0][0]);
            bB[b][p] = smem_u32(&Bs[b][p][0][0]);
        }

    float acc[2][8][4];
#pragma unroll
    for (int mt = 0; mt < 2; mt++)
#pragma unroll
        for (int nt = 0; nt < 8; nt++)
#pragma unroll
            for (int q = 0; q < 4; q++) acc[mt][nt][q] = 0.f;

    int lrow = t >> 1, lhalf = t & 1;
    uint32_t doff = (uint32_t)(lrow*32 + (((lhalf ^ (lrow >> 2)) & 1) << 4));

    auto load_chunk = [&](int kc, int buf) {
        size_t ko = (size_t)kc*16 + lhalf*8;
#pragma unroll
        for (int pl = 0; pl < 3; pl++) {
            cpasync16(aB[buf][pl] + doff,
                      g_featB + ((size_t)pl*Nt + m0 + lrow)*KPS + ko);
            cpasync16(bB[buf][pl] + doff,
                      g_wB + ((size_t)(dir*3 + pl)*G4 + n0 + lrow)*KPS + ko);
        }
        cpcommit();
    };

    load_chunk(0, 0);

    int lr = lane & 15;
    uint32_t lmo = (uint32_t)(lr*32 + ((((lane >> 4) ^ (lr >> 2)) & 1) << 4));

    for (int c = 0; c < NCH; c++) {
        int buf = c & 1;
        if (c + 1 < NCH) {
            load_chunk(c + 1, buf ^ 1);
            asm volatile("cp.async.wait_group 1;");
        } else {
            asm volatile("cp.async.wait_group 0;");
        }
        __syncthreads();

#pragma unroll
        for (int pb = 0; pb < 3; pb++) {
            uint32_t bfr[4][4];
#pragma unroll
            for (int np = 0; np < 4; np++)
                LDSM4(bfr[np], bB[buf][pb] + (uint32_t)((wn*64 + np*16)*32) + lmo);
#pragma unroll
            for (int pa = 0; pa <= 2 - pb; pa++) {
                uint32_t a0[4], a1[4];
                LDSM4(a0, aB[buf][pa] + (uint32_t)((wm*32)*32) + lmo);
                LDSM4(a1, aB[buf][pa] + (uint32_t)((wm*32 + 16)*32) + lmo);
#pragma unroll
                for (int nt = 0; nt < 8; nt++) {
                    uint32_t b0 = bfr[nt >> 1][nt & 1];
                    uint32_t b1 = bfr[nt >> 1][2 + (nt & 1)];
                    mma_bf16(acc[0][nt], a0, b0, b1);
                    mma_bf16(acc[1][nt], a1, b0, b1);
                }
            }
        }
        __syncthreads();
    }

#pragma unroll
    for (int mt = 0; mt < 2; mt++) {
        size_t r0 = (size_t)(m0 + wm*32 + mt*16 + gi);
#pragma unroll
        for (int nt = 0; nt < 8; nt++) {
            int col = n0 + wn*64 + nt*8 + 2*li;
            float b0 = bias[col], b1 = bias[col + 1];
            float2 v;
            v.x = acc[mt][nt][0] + b0; v.y = acc[mt][nt][1] + b1;
            *(float2*)(Co + r0*G4 + col) = v;
            v.x = acc[mt][nt][2] + b0; v.y = acc[mt][nt][3] + b1;
            *(float2*)(Co + (r0 + 8)*G4 + col) = v;
        }
    }
}

// ======================= LSTM recurrence (both dirs fused, f32x2) =======================
__global__ __launch_bounds__(256, 2) void lstm_fused()
{
    int dir = blockIdx.x >> 7;
    int blk = blockIdx.x & 127;
    const float* __restrict__ gates = g_gates[dir];
    const float* __restrict__ whhT  = g_whhT[dir];
    float* __restrict__ hout        = g_h[dir];

    __shared__ __align__(16) float hs[2][Hm][36];

    int t = threadIdx.x;
    int j = t & 127;
    int half = t >> 7;
    int r0 = blk * 32 + half * 16;

    for (int i = t; i < 2*Hm*36; i += 256) ((float*)hs)[i] = 0.f;

    float cst[16];
#pragma unroll
    for (int r = 0; r < 16; r++) cst[r] = 0.f;
    __syncthreads();

    int cur = 0;
    const float* wp = whhT + j;

    for (int li = 0; li < Lm; li++) {
        int l = dir ? (Lm-1-li) : li;

        u64 acc2[4][8];
#pragma unroll
        for (int g = 0; g < 4; g++)
#pragma unroll
            for (int q = 0; q < 8; q++) {
                size_t base = ((size_t)(r0 + 2*q)*Lm + l)*G4 + g*128 + j;
                float lo = gates[base];
                float hi = gates[base + (size_t)Lm*G4];
                acc2[g][q] = pack2(lo, hi);
            }

#pragma unroll 4
        for (int k = 0; k < Hm; k++) {
            float w0 = wp[k*G4 + 0];
            float w1 = wp[k*G4 + 128];
            float w2 = wp[k*G4 + 256];
            float w3 = wp[k*G4 + 384];
            u64 w0p = splat2(w0), w1p = splat2(w1);
            u64 w2p = splat2(w2), w3p = splat2(w3);
            const ulonglong2* hp = (const ulonglong2*)&hs[cur][k][half*16];
#pragma unroll
            for (int qq = 0; qq < 4; qq++) {
                ulonglong2 hv2 = hp[qq];
                acc2[0][2*qq]   = fma2(w0p, hv2.x, acc2[0][2*qq]);
                acc2[1][2*qq]   = fma2(w1p, hv2.x, acc2[1][2*qq]);
                acc2[2][2*qq]   = fma2(w2p, hv2.x, acc2[2][2*qq]);
                acc2[3][2*qq]   = fma2(w3p, hv2.x, acc2[3][2*qq]);
                acc2[0][2*qq+1] = fma2(w0p, hv2.y, acc2[0][2*qq+1]);
                acc2[1][2*qq+1] = fma2(w1p, hv2.y, acc2[1][2*qq+1]);
                acc2[2][2*qq+1] = fma2(w2p, hv2.y, acc2[2][2*qq+1]);
                acc2[3][2*qq+1] = fma2(w3p, hv2.y, acc2[3][2*qq+1]);
            }
        }

#pragma unroll
        for (int q = 0; q < 8; q++) {
            float zi0,zi1,zf0,zf1,zg0,zg1,zo0,zo1;
            unpack2(acc2[0][q], zi0, zi1);
            unpack2(acc2[1][q], zf0, zf1);
            unpack2(acc2[2][q], zg0, zg1);
            unpack2(acc2[3][q], zo0, zo1);
            {
                float ig = sigf(zi0), fg = sigf(zf0);
                float gg = tanhfast(zg0), og = sigf(zo0);
                float cn = fg*cst[2*q] + ig*gg;
                cst[2*q] = cn;
                float hn = og * tanhfast(cn);
                hs[cur^1][j][half*16 + 2*q] = hn;
                hout[((size_t)(r0 + 2*q)*Lm + l)*Hm + j] = hn;
            }
            {
                float ig = sigf(zi1), fg = sigf(zf1);
                float gg = tanhfast(zg1), og = sigf(zo1);
                float cn = fg*cst[2*q+1] + ig*gg;
                cst[2*q+1] = cn;
                float hn = og * tanhfast(cn);
                hs[cur^1][j][half*16 + 2*q + 1] = hn;
                hout[((size_t)(r0 + 2*q + 1)*Lm + l)*Hm + j] = hn;
            }
        }
        cur ^= 1;
        __syncthreads();
    }
}

// ======================= emission (BN2+FC folded) =======================
__global__ void emission_kernel()
{
    int gt = blockIdx.x*blockDim.x + threadIdx.x;
    int warp = gt >> 5;
    int lane = threadIdx.x & 31;
    if (warp >= Nt) return;
    float4 hf4 = *(const float4*)&g_h[0][(size_t)warp*Hm + lane*4];
    float4 hb4 = *(const float4*)&g_h[1][(size_t)warp*Hm + lane*4];
#pragma unroll
    for (int tt = 0; tt < Tm; tt++) {
        float4 f4 = *(const float4*)&g_fcf[tt*Hm + lane*4];
        float4 b4 = *(const float4*)&g_fcb[tt*Hm + lane*4];
        float s = hf4.x*f4.x + hf4.y*f4.y + hf4.z*f4.z + hf4.w*f4.w
                + hb4.x*b4.x + hb4.y*b4.y + hb4.z*b4.z + hb4.w*b4.w;
#pragma unroll
        for (int o = 16; o; o >>= 1) s += __shfl_xor_sync(0xffffffffu, s, o);
        if (lane == 0) g_emis[(size_t)warp*Tm + tt] = s + g_cbias[tt];
    }
}

// ======================= Viterbi =======================
__global__ void viterbi_kernel(const int* __restrict__ x,
                               const float* __restrict__ trans,
                               const float* __restrict__ start_t,
                               const float* __restrict__ end_t,
                               float* __restrict__ out)
{
    int b = blockIdx.x*blockDim.x + threadIdx.x;
    if (b >= Bsz) return;
    float tr[9];
#pragma unroll
    for (int i = 0; i < 9; i++) tr[i] = trans[i];
    const float* em = g_emis + (size_t)b*Lm*Tm;
    float sc[3];
#pragma unroll
    for (int t = 0; t < 3; t++) sc[t] = start_t[t] + em[t];

    unsigned char hist[Lm-1][3];
    for (int l = 1; l < Lm; l++) {
        bool m = x[(b*Lm + l)*Wm + 2] > 0;
        float ns[3];
#pragma unroll
        for (int t = 0; t < 3; t++) {
            float best = sc[0] + tr[0*3 + t];
            int bp = 0;
#pragma unroll
            for (int p = 1; p < 3; p++) {
                float v = sc[p] + tr[p*3 + t];
                if (v > best) { best = v; bp = p; }
            }
            hist[l-1][t] = (unsigned char)bp;
            ns[t] = best + em[l*Tm + t];
        }
        if (m) { sc[0]=ns[0]; sc[1]=ns[1]; sc[2]=ns[2]; }
    }
#pragma unroll
    for (int t = 0; t < 3; t++) sc[t] += end_t[t];
    float best = sc[0]; int last = 0;
    if (sc[1] > best) { best = sc[1]; last = 1; }
    if (sc[2] > best) { best = sc[2]; last = 2; }
    out[b] = best;

    float* tagout = out + Bsz;
    int tag = last;
    tagout[(size_t)b*Lm + (Lm-1)] = (float)tag;
    for (int i = Lm-2; i >= 0; i--) {
        int prev = hist[i][tag];
        bool m = x[(b*Lm + i + 1)*Wm + 2] > 0;
        if (m) tag = prev;
        tagout[(size_t)b*Lm + i] = (float)tag;
    }
}

// ======================= launch =======================
extern "C" void kernel_launch(void* const* d_in, const int* in_sizes, int n_in,
                              void* d_out, int out_size)
{
    (void)in_sizes; (void)n_in; (void)out_size;
    const int*   x      = (const int*)  d_in[0];
    const float* emb    = (const float*)d_in[1];
    const float* conv_w = (const float*)d_in[2];
    const float* conv_b = (const float*)d_in[3];
    const float* bn1_g  = (const float*)d_in[4];
    const float* bn1_b  = (const float*)d_in[5];
    const float* bn1_m  = (const float*)d_in[6];
    const float* bn1_v  = (const float*)d_in[7];
    const float* w_ih_f = (const float*)d_in[8];
    const float* w_hh_f = (const float*)d_in[9];
    const float* b_f    = (const float*)d_in[10];
    const float* w_ih_b = (const float*)d_in[11];
    const float* w_hh_b = (const float*)d_in[12];
    const float* b_b    = (const float*)d_in[13];
    const float* bn2_g  = (const float*)d_in[14];
    const float* bn2_b  = (const float*)d_in[15];
    const float* bn2_m  = (const float*)d_in[16];
    const float* bn2_v  = (const float*)d_in[17];
    const float* fc_w   = (const float*)d_in[18];
    const float* fc_b   = (const float*)d_in[19];
    const float* trans  = (const float*)d_in[20];
    const float* start_t= (const float*)d_in[21];
    const float* end_t  = (const float*)d_in[22];
    float* out = (float*)d_out;

    prep_tables<<<(Am*Cch*3 + Cch + 255)/256, 256>>>(emb, conv_w, conv_b,
                                                     bn1_g, bn1_b, bn1_m, bn1_v);
    prep_pack5<<<512, 256>>>(w_ih_f, w_hh_f, w_ih_b, w_hh_b);
    prep_fc<<<1, 256>>>(bn2_g, bn2_b, bn2_m, bn2_v, fc_w, fc_b);

    dim3 fg(Nt/256, Cch);
    featurizeT<<<fg, 256>>>(x);

    dim3 sg(Nt/64, KPS/64);
    split_planes<<<sg, 256>>>();

    dim3 gg(8, Nt/128);
    gemm_bf16s<<<gg, 256>>>(b_f, b_b);

    lstm_fused<<<256, 256>>>();

    emission_kernel<<<(Nt + 3)/4, 128>>>();

    viterbi_kernel<<<(Bsz + 127)/128, 128>>>(x, trans, start_t, end_t, out);
}

// round 10
// speedup vs baseline: 1.2564x; 1.2564x over previous
#include <cuda_runtime.h>
#include <cuda_fp16.h>
#include <math.h>
#include <stdint.h>

// ---- problem constants ----
#define Bsz 4096
#define Lm  30
#define Wm  5
#define Am  30
#define Em  128
#define Cch 40
#define Hm  128
#define Tm  3
#define LIN 200
#define FK  208          // valid K
#define KPS 256          // padded K stride for fp16 planes
#define Nt  (Bsz*Lm)     // 122880 tokens
#define G4  512          // 4*H gates
#define NCH 13           // 208/16 k-chunks

typedef unsigned long long u64;

// ---- packed f32x2 helpers (FFMA2 path) ----
__device__ __forceinline__ u64 pack2(float lo, float hi) {
    u64 r; asm("mov.b64 %0,{%1,%2};" : "=l"(r) : "f"(lo), "f"(hi)); return r;
}
__device__ __forceinline__ u64 splat2(float v) { return pack2(v, v); }
__device__ __forceinline__ u64 fma2(u64 a, u64 b, u64 c) {
    u64 d; asm("fma.rn.f32x2 %0,%1,%2,%3;" : "=l"(d) : "l"(a), "l"(b), "l"(c)); return d;
}
__device__ __forceinline__ void unpack2(u64 v, float& lo, float& hi) {
    asm("mov.b64 {%0,%1},%2;" : "=f"(lo), "=f"(hi) : "l"(v));
}
__device__ __forceinline__ float sigf(float x) {
    return __fdividef(1.f, 1.f + __expf(-x));
}
__device__ __forceinline__ float tanhfast(float x) {
    return __fdividef(2.f, 1.f + __expf(-2.f * x)) - 1.f;
}
__device__ __forceinline__ void cpasync16(uint32_t smem, const void* gmem) {
    asm volatile("cp.async.ca.shared.global [%0],[%1],16;" :: "r"(smem), "l"(gmem));
}
__device__ __forceinline__ void cpcommit() {
    asm volatile("cp.async.commit_group;");
}
__device__ __forceinline__ uint32_t smem_u32(const void* p) {
    uint32_t a;
    asm("{ .reg .u64 t; cvta.to.shared.u64 t, %1; cvt.u32.u64 %0, t; }" : "=r"(a) : "l"(p));
    return a;
}
__device__ __forceinline__ void split2h(float v, __half& h, __half& l) {
    h = __float2half_rn(v);
    l = __float2half_rn(v - __half2float(h));
}
#define LDSM4(d, addr) \
    asm volatile("ldmatrix.sync.aligned.m8n8.x4.shared.b16 {%0,%1,%2,%3},[%4];" \
        : "=r"((d)[0]), "=r"((d)[1]), "=r"((d)[2]), "=r"((d)[3]) : "r"(addr))
__device__ __forceinline__ void mma_f16(float* d, const uint32_t* a, uint32_t b0, uint32_t b1) {
    asm volatile(
        "mma.sync.aligned.m16n8k16.row.col.f32.f16.f16.f32 "
        "{%0,%1,%2,%3},{%4,%5,%6,%7},{%8,%9},{%0,%1,%2,%3};"
        : "+f"(d[0]), "+f"(d[1]), "+f"(d[2]), "+f"(d[3])
        : "r"(a[0]), "r"(a[1]), "r"(a[2]), "r"(a[3]), "r"(b0), "r"(b1));
}

// ---- device scratch ----
__device__ float g_M[Am*Cch*3];
__device__ float g_bias1[Cch];
__device__ __align__(128) __half g_wH[2*2*(size_t)G4*KPS];     // [dir*2+plane][g][k]
__device__ float g_whhT[2][Hm*G4];
__device__ float g_fcf[Tm*Hm];
__device__ float g_fcb[Tm*Hm];
__device__ float g_cbias[Tm];
__device__ float g_featT[(size_t)FK*Nt];                        // k-major fp32 staging
__device__ __align__(128) __half g_featH[2*(size_t)Nt*KPS];    // [plane][n][k]
__device__ float g_gates[2][(size_t)Nt*G4];
__device__ float g_h[2][(size_t)Nt*Hm];
__device__ float g_emis[(size_t)Nt*Tm];

// ======================= prep kernels =======================
__global__ void prep_tables(const float* __restrict__ emb,
                            const float* __restrict__ conv_w,
                            const float* __restrict__ conv_b,
                            const float* __restrict__ g1,
                            const float* __restrict__ b1,
                            const float* __restrict__ m1,
                            const float* __restrict__ v1)
{
    int i = blockIdx.x*blockDim.x + threadIdx.x;
    if (i < Am*Cch*3) {
        int k = i % 3;
        int c = (i/3) % Cch;
        int a = i / (3*Cch);
        float s = 0.f;
        for (int e = 0; e < Em; e++)
            s += emb[a*Em + e] * conv_w[(c*Em + e)*3 + k];
        float sc = g1[c] * rsqrtf(v1[c] + 1e-5f);
        g_M[i] = s * sc;
    } else if (i < Am*Cch*3 + Cch) {
        int c = i - Am*Cch*3;
        float sc = g1[c] * rsqrtf(v1[c] + 1e-5f);
        g_bias1[c] = (conv_b[c] - m1[c]) * sc + b1[c];
    }
}

__global__ void prep_pack6(const float* __restrict__ wihf, const float* __restrict__ whhf,
                           const float* __restrict__ wihb, const float* __restrict__ whhb)
{
    int stride = gridDim.x * blockDim.x;
    int t0 = blockIdx.x*blockDim.x + threadIdx.x;
    for (int i = t0; i < G4*KPS; i += stride) {
        int g = i / KPS, k = i % KPS;
        float vf = (k < LIN) ? wihf[g*LIN + k] : 0.f;
        float vb = (k < LIN) ? wihb[g*LIN + k] : 0.f;
        __half h, l;
        split2h(vf, h, l);
        g_wH[(size_t)(0*2+0)*G4*KPS + i] = h;
        g_wH[(size_t)(0*2+1)*G4*KPS + i] = l;
        split2h(vb, h, l);
        g_wH[(size_t)(1*2+0)*G4*KPS + i] = h;
        g_wH[(size_t)(1*2+1)*G4*KPS + i] = l;
    }
    for (int i = t0; i < Hm*G4; i += stride) {
        int k = i / G4, g = i % G4;
        g_whhT[0][i] = whhf[g*Hm + k];
        g_whhT[1][i] = whhb[g*Hm + k];
    }
}

__global__ void prep_fc(const float* __restrict__ g2, const float* __restrict__ b2,
                        const float* __restrict__ m2, const float* __restrict__ v2,
                        const float* __restrict__ fcw, const float* __restrict__ fcbias)
{
    int t = threadIdx.x;
    if (t < Hm) {
        float s2a = g2[t]       * rsqrtf(v2[t]       + 1e-5f);
        float s2b = g2[Hm + t]  * rsqrtf(v2[Hm + t]  + 1e-5f);
        for (int tt = 0; tt < Tm; tt++) {
            g_fcf[tt*Hm + t] = fcw[tt*2*Hm + t]      * s2a;
            g_fcb[tt*Hm + t] = fcw[tt*2*Hm + Hm + t] * s2b;
        }
    }
    if (t < Tm) {
        float s = fcbias[t];
        for (int j = 0; j < 2*Hm; j++) {
            float s2 = g2[j] * rsqrtf(v2[j] + 1e-5f);
            s += (b2[j] - m2[j]*s2) * fcw[t*2*Hm + j];
        }
        g_cbias[t] = s;
    }
}

// ======================= featurize (conv+bn+relu+pool), k-major fp32 =======================
__global__ void featurizeT(const int* __restrict__ x)
{
    int n = blockIdx.x*blockDim.x + threadIdx.x;
    int c = blockIdx.y;
    if (n >= Nt) return;
    int sym[Wm];
#pragma unroll
    for (int w = 0; w < Wm; w++) sym[w] = x[n*Wm + w];
    float y[Wm];
    float bb = g_bias1[c];
#pragma unroll
    for (int w = 0; w < Wm; w++) {
        float v = bb;
#pragma unroll
        for (int k = 0; k < 3; k++) {
            int p = w + k - 1;
            if (p >= 0 && p < Wm)
                v += g_M[sym[p]*(Cch*3) + c*3 + k];
        }
        y[w] = fmaxf(v, 0.f);
    }
#pragma unroll
    for (int w = 0; w < Wm; w++) {
        float p = y[w];
        if (w > 0)      p = fmaxf(p, y[w-1]);
        if (w < Wm-1)   p = fmaxf(p, y[w+1]);
        g_featT[(size_t)(c*Wm + w)*Nt + n] = p;
    }
    if (c == 0) {
#pragma unroll
        for (int k = LIN; k < FK; k++)
            g_featT[(size_t)k*Nt + n] = 0.f;
    }
}

// ======================= transpose + fp16 2-split: [k][n] f32 -> [plane][n][k] fp16 =======================
__global__ __launch_bounds__(256) void split_planes()
{
    __shared__ float tile[64][65];
    int tn0 = blockIdx.x * 64;
    int tk0 = blockIdx.y * 64;
    int t = threadIdx.x;
#pragma unroll
    for (int i = 0; i < 16; i++) {
        int idx = t + i*256;
        int kk = idx >> 6, nn = idx & 63;
        float v = (tk0 + kk < FK) ? g_featT[(size_t)(tk0 + kk)*Nt + tn0 + nn] : 0.f;
        tile[kk][nn] = v;
    }
    __syncthreads();
    int n  = t >> 2;
    int kg = t & 3;
    uint32_t wh[8], wl[8];
#pragma unroll
    for (int j = 0; j < 8; j++) {
        __half h0, l0, h1, l1;
        split2h(tile[kg*16 + 2*j][n],     h0, l0);
        split2h(tile[kg*16 + 2*j + 1][n], h1, l1);
        wh[j] = (uint32_t)__half_as_ushort(h0) | ((uint32_t)__half_as_ushort(h1) << 16);
        wl[j] = (uint32_t)__half_as_ushort(l0) | ((uint32_t)__half_as_ushort(l1) << 16);
    }
    size_t ob = (size_t)(tn0 + n)*KPS + tk0 + kg*16;
    uint4* d0 = (uint4*)(g_featH + ob);
    uint4* d1 = (uint4*)(g_featH + (size_t)Nt*KPS + ob);
    d0[0] = make_uint4(wh[0], wh[1], wh[2], wh[3]);
    d0[1] = make_uint4(wh[4], wh[5], wh[6], wh[7]);
    d1[0] = make_uint4(wl[0], wl[1], wl[2], wl[3]);
    d1[1] = make_uint4(wl[4], wl[5], wl[6], wl[7]);
}

// ======================= input GEMM v9: fp16 2-plane split, mma.m16n8k16 + ldmatrix =======================
// 128x128 block, 8 warps (wm=w&3 -> 32 M rows, wn=w>>2 -> 64 N cols).
// 3 split terms: ah*bh, al*bh, ah*bl.
// Smem: 2 buf x 2 planes x (A 128x16 + B 128x16) fp16 = 32KB static.
// Row stride 32B; XOR swizzle: half ^= (row>>2)&1 -> conflict-free LDSM + cp.async.
__global__ __launch_bounds__(256, 2) void gemm_f16s(const float* __restrict__ bias_f,
                                                    const float* __restrict__ bias_b)
{
    __shared__ __align__(16) __half As[2][2][128][16];
    __shared__ __align__(16) __half Bs[2][2][128][16];

    int dir = blockIdx.x >> 2;
    int n0  = (blockIdx.x & 3) * 128;
    int m0  = blockIdx.y * 128;
    const float* __restrict__ bias = dir ? bias_b : bias_f;
    float* __restrict__ Co = g_gates[dir];

    int t = threadIdx.x, lane = t & 31, w = t >> 5;
    int wm = w & 3, wn = w >> 2;
    int gi = lane >> 2, li = lane & 3;

    uint32_t aB[2][2], bB[2][2];
#pragma unroll
    for (int b = 0; b < 2; b++)
#pragma unroll
        for (int p = 0; p < 2; p++) {
            aB[b][p] = smem_u32(&As[b][p][0][0]);
            bB[b][p] = smem_u32(&Bs[b][p][0][0]);
        }

    float acc[2][8][4];
#pragma unroll
    for (int mt = 0; mt < 2; mt++)
#pragma unroll
        for (int nt = 0; nt < 8; nt++)
#pragma unroll
            for (int q = 0; q < 4; q++) acc[mt][nt][q] = 0.f;

    int lrow = t >> 1, lhalf = t & 1;
    uint32_t doff = (uint32_t)(lrow*32 + (((lhalf ^ (lrow >> 2)) & 1) << 4));

    auto load_chunk = [&](int kc, int buf) {
        size_t ko = (size_t)kc*16 + lhalf*8;
#pragma unroll
        for (int pl = 0; pl < 2; pl++) {
            cpasync16(aB[buf][pl] + doff,
                      g_featH + ((size_t)pl*Nt + m0 + lrow)*KPS + ko);
            cpasync16(bB[buf][pl] + doff,
                      g_wH + ((size_t)(dir*2 + pl)*G4 + n0 + lrow)*KPS + ko);
        }
        cpcommit();
    };

    load_chunk(0, 0);

    int lr = lane & 15;
    uint32_t lmo = (uint32_t)(lr*32 + ((((lane >> 4) ^ (lr >> 2)) & 1) << 4));

    for (int c = 0; c < NCH; c++) {
        int buf = c & 1;
        if (c + 1 < NCH) {
            load_chunk(c + 1, buf ^ 1);
            asm volatile("cp.async.wait_group 1;");
        } else {
            asm volatile("cp.async.wait_group 0;");
        }
        __syncthreads();

        uint32_t bh[4][4], bl[4][4];
#pragma unroll
        for (int np = 0; np < 4; np++) {
            LDSM4(bh[np], bB[buf][0] + (uint32_t)((wn*64 + np*16)*32) + lmo);
            LDSM4(bl[np], bB[buf][1] + (uint32_t)((wn*64 + np*16)*32) + lmo);
        }
        uint32_t ah0[4], ah1[4], al0[4], al1[4];
        LDSM4(ah0, aB[buf][0] + (uint32_t)((wm*32)*32) + lmo);
        LDSM4(ah1, aB[buf][0] + (uint32_t)((wm*32 + 16)*32) + lmo);
        LDSM4(al0, aB[buf][1] + (uint32_t)((wm*32)*32) + lmo);
        LDSM4(al1, aB[buf][1] + (uint32_t)((wm*32 + 16)*32) + lmo);

#pragma unroll
        for (int nt = 0; nt < 8; nt++) {
            uint32_t b0h = bh[nt >> 1][nt & 1];
            uint32_t b1h = bh[nt >> 1][2 + (nt & 1)];
            uint32_t b0l = bl[nt >> 1][nt & 1];
            uint32_t b1l = bl[nt >> 1][2 + (nt & 1)];
            mma_f16(acc[0][nt], ah0, b0h, b1h);
            mma_f16(acc[1][nt], ah1, b0h, b1h);
            mma_f16(acc[0][nt], al0, b0h, b1h);
            mma_f16(acc[1][nt], al1, b0h, b1h);
            mma_f16(acc[0][nt], ah0, b0l, b1l);
            mma_f16(acc[1][nt], ah1, b0l, b1l);
        }
        __syncthreads();
    }

#pragma unroll
    for (int mt = 0; mt < 2; mt++) {
        size_t r0 = (size_t)(m0 + wm*32 + mt*16 + gi);
#pragma unroll
        for (int nt = 0; nt < 8; nt++) {
            int col = n0 + wn*64 + nt*8 + 2*li;
            float b0 = bias[col], b1 = bias[col + 1];
            float2 v;
            v.x = acc[mt][nt][0] + b0; v.y = acc[mt][nt][1] + b1;
            *(float2*)(Co + r0*G4 + col) = v;
            v.x = acc[mt][nt][2] + b0; v.y = acc[mt][nt][3] + b1;
            *(float2*)(Co + (r0 + 8)*G4 + col) = v;
        }
    }
}

// ======================= LSTM recurrence (both dirs fused, f32x2) =======================
__global__ __launch_bounds__(256, 2) void lstm_fused()
{
    int dir = blockIdx.x >> 7;
    int blk = blockIdx.x & 127;
    const float* __restrict__ gates = g_gates[dir];
    const float* __restrict__ whhT  = g_whhT[dir];
    float* __restrict__ hout        = g_h[dir];

    __shared__ __align__(16) float hs[2][Hm][36];

    int t = threadIdx.x;
    int j = t & 127;
    int half = t >> 7;
    int r0 = blk * 32 + half * 16;

    for (int i = t; i < 2*Hm*36; i += 256) ((float*)hs)[i] = 0.f;

    float cst[16];
#pragma unroll
    for (int r = 0; r < 16; r++) cst[r] = 0.f;
    __syncthreads();

    int cur = 0;
    const float* wp = whhT + j;

    for (int li = 0; li < Lm; li++) {
        int l = dir ? (Lm-1-li) : li;

        u64 acc2[4][8];
#pragma unroll
        for (int g = 0; g < 4; g++)
#pragma unroll
            for (int q = 0; q < 8; q++) {
                size_t base = ((size_t)(r0 + 2*q)*Lm + l)*G4 + g*128 + j;
                float lo = gates[base];
                float hi = gates[base + (size_t)Lm*G4];
                acc2[g][q] = pack2(lo, hi);
            }

#pragma unroll 4
        for (int k = 0; k < Hm; k++) {
            float w0 = wp[k*G4 + 0];
            float w1 = wp[k*G4 + 128];
            float w2 = wp[k*G4 + 256];
            float w3 = wp[k*G4 + 384];
            u64 w0p = splat2(w0), w1p = splat2(w1);
            u64 w2p = splat2(w2), w3p = splat2(w3);
            const ulonglong2* hp = (const ulonglong2*)&hs[cur][k][half*16];
#pragma unroll
            for (int qq = 0; qq < 4; qq++) {
                ulonglong2 hv2 = hp[qq];
                acc2[0][2*qq]   = fma2(w0p, hv2.x, acc2[0][2*qq]);
                acc2[1][2*qq]   = fma2(w1p, hv2.x, acc2[1][2*qq]);
                acc2[2][2*qq]   = fma2(w2p, hv2.x, acc2[2][2*qq]);
                acc2[3][2*qq]   = fma2(w3p, hv2.x, acc2[3][2*qq]);
                acc2[0][2*qq+1] = fma2(w0p, hv2.y, acc2[0][2*qq+1]);
                acc2[1][2*qq+1] = fma2(w1p, hv2.y, acc2[1][2*qq+1]);
                acc2[2][2*qq+1] = fma2(w2p, hv2.y, acc2[2][2*qq+1]);
                acc2[3][2*qq+1] = fma2(w3p, hv2.y, acc2[3][2*qq+1]);
            }
        }

#pragma unroll
        for (int q = 0; q < 8; q++) {
            float zi0,zi1,zf0,zf1,zg0,zg1,zo0,zo1;
            unpack2(acc2[0][q], zi0, zi1);
            unpack2(acc2[1][q], zf0, zf1);
            unpack2(acc2[2][q], zg0, zg1);
            unpack2(acc2[3][q], zo0, zo1);
            {
                float ig = sigf(zi0), fg = sigf(zf0);
                float gg = tanhfast(zg0), og = sigf(zo0);
                float cn = fg*cst[2*q] + ig*gg;
                cst[2*q] = cn;
                float hn = og * tanhfast(cn);
                hs[cur^1][j][half*16 + 2*q] = hn;
                hout[((size_t)(r0 + 2*q)*Lm + l)*Hm + j] = hn;
            }
            {
                float ig = sigf(zi1), fg = sigf(zf1);
                float gg = tanhfast(zg1), og = sigf(zo1);
                float cn = fg*cst[2*q+1] + ig*gg;
                cst[2*q+1] = cn;
                float hn = og * tanhfast(cn);
                hs[cur^1][j][half*16 + 2*q + 1] = hn;
                hout[((size_t)(r0 + 2*q + 1)*Lm + l)*Hm + j] = hn;
            }
        }
        cur ^= 1;
        __syncthreads();
    }
}

// ======================= emission (BN2+FC folded) =======================
__global__ void emission_kernel()
{
    int gt = blockIdx.x*blockDim.x + threadIdx.x;
    int warp = gt >> 5;
    int lane = threadIdx.x & 31;
    if (warp >= Nt) return;
    float4 hf4 = *(const float4*)&g_h[0][(size_t)warp*Hm + lane*4];
    float4 hb4 = *(const float4*)&g_h[1][(size_t)warp*Hm + lane*4];
#pragma unroll
    for (int tt = 0; tt < Tm; tt++) {
        float4 f4 = *(const float4*)&g_fcf[tt*Hm + lane*4];
        float4 b4 = *(const float4*)&g_fcb[tt*Hm + lane*4];
        float s = hf4.x*f4.x + hf4.y*f4.y + hf4.z*f4.z + hf4.w*f4.w
                + hb4.x*b4.x + hb4.y*b4.y + hb4.z*b4.z + hb4.w*b4.w;
#pragma unroll
        for (int o = 16; o; o >>= 1) s += __shfl_xor_sync(0xffffffffu, s, o);
        if (lane == 0) g_emis[(size_t)warp*Tm + tt] = s + g_cbias[tt];
    }
}

// ======================= Viterbi =======================
__global__ void viterbi_kernel(const int* __restrict__ x,
                               const float* __restrict__ trans,
                               const float* __restrict__ start_t,
                               const float* __restrict__ end_t,
                               float* __restrict__ out)
{
    int b = blockIdx.x*blockDim.x + threadIdx.x;
    if (b >= Bsz) return;
    float tr[9];
#pragma unroll
    for (int i = 0; i < 9; i++) tr[i] = trans[i];
    const float* em = g_emis + (size_t)b*Lm*Tm;
    float sc[3];
#pragma unroll
    for (int t = 0; t < 3; t++) sc[t] = start_t[t] + em[t];

    unsigned char hist[Lm-1][3];
    for (int l = 1; l < Lm; l++) {
        bool m = x[(b*Lm + l)*Wm + 2] > 0;
        float ns[3];
#pragma unroll
        for (int t = 0; t < 3; t++) {
            float best = sc[0] + tr[0*3 + t];
            int bp = 0;
#pragma unroll
            for (int p = 1; p < 3; p++) {
                float v = sc[p] + tr[p*3 + t];
                if (v > best) { best = v; bp = p; }
            }
            hist[l-1][t] = (unsigned char)bp;
            ns[t] = best + em[l*Tm + t];
        }
        if (m) { sc[0]=ns[0]; sc[1]=ns[1]; sc[2]=ns[2]; }
    }
#pragma unroll
    for (int t = 0; t < 3; t++) sc[t] += end_t[t];
    float best = sc[0]; int last = 0;
    if (sc[1] > best) { best = sc[1]; last = 1; }
    if (sc[2] > best) { best = sc[2]; last = 2; }
    out[b] = best;

    float* tagout = out + Bsz;
    int tag = last;
    tagout[(size_t)b*Lm + (Lm-1)] = (float)tag;
    for (int i = Lm-2; i >= 0; i--) {
        int prev = hist[i][tag];
        bool m = x[(b*Lm + i + 1)*Wm + 2] > 0;
        if (m) tag = prev;
        tagout[(size_t)b*Lm + i] = (float)tag;
    }
}

// ======================= launch =======================
extern "C" void kernel_launch(void* const* d_in, const int* in_sizes, int n_in,
                              void* d_out, int out_size)
{
    (void)in_sizes; (void)n_in; (void)out_size;
    const int*   x      = (const int*)  d_in[0];
    const float* emb    = (const float*)d_in[1];
    const float* conv_w = (const float*)d_in[2];
    const float* conv_b = (const float*)d_in[3];
    const float* bn1_g  = (const float*)d_in[4];
    const float* bn1_b  = (const float*)d_in[5];
    const float* bn1_m  = (const float*)d_in[6];
    const float* bn1_v  = (const float*)d_in[7];
    const float* w_ih_f = (const float*)d_in[8];
    const float* w_hh_f = (const float*)d_in[9];
    const float* b_f    = (const float*)d_in[10];
    const float* w_ih_b = (const float*)d_in[11];
    const float* w_hh_b = (const float*)d_in[12];
    const float* b_b    = (const float*)d_in[13];
    const float* bn2_g  = (const float*)d_in[14];
    const float* bn2_b  = (const float*)d_in[15];
    const float* bn2_m  = (const float*)d_in[16];
    const float* bn2_v  = (const float*)d_in[17];
    const float* fc_w   = (const float*)d_in[18];
    const float* fc_b   = (const float*)d_in[19];
    const float* trans  = (const float*)d_in[20];
    const float* start_t= (const float*)d_in[21];
    const float* end_t  = (const float*)d_in[22];
    float* out = (float*)d_out;

    prep_tables<<<(Am*Cch*3 + Cch + 255)/256, 256>>>(emb, conv_w, conv_b,
                                                     bn1_g, bn1_b, bn1_m, bn1_v);
    prep_pack6<<<512, 256>>>(w_ih_f, w_hh_f, w_ih_b, w_hh_b);
    prep_fc<<<1, 256>>>(bn2_g, bn2_b, bn2_m, bn2_v, fc_w, fc_b);

    dim3 fg(Nt/256, Cch);
    featurizeT<<<fg, 256>>>(x);

    dim3 sg(Nt/64, KPS/64);
    split_planes<<<sg, 256>>>();

    dim3 gg(8, Nt/128);
    gemm_f16s<<<gg, 256>>>(b_f, b_b);

    lstm_fused<<<256, 256>>>();

    emission_kernel<<<(Nt + 3)/4, 128>>>();

    viterbi_kernel<<<(Bsz + 127)/128, 128>>>(x, trans, start_t, end_t, out);
}

// round 11
// speedup vs baseline: 1.2916x; 1.0280x over previous
#include <cuda_runtime.h>
#include <cuda_fp16.h>
#include <math.h>
#include <stdint.h>

// ---- problem constants ----
#define Bsz 4096
#define Lm  30
#define Wm  5
#define Am  30
#define Em  128
#define Cch 40
#define Hm  128
#define Tm  3
#define LIN 200
#define KPS 224          // padded K stride for fp16 planes (7 x 32)
#define Nt  (Bsz*Lm)     // 122880 tokens
#define G4  512          // 4*H gates
#define NCH 7            // 224/32 k-chunks

typedef unsigned long long u64;

// ---- packed f32x2 helpers (FFMA2 path) ----
__device__ __forceinline__ u64 pack2(float lo, float hi) {
    u64 r; asm("mov.b64 %0,{%1,%2};" : "=l"(r) : "f"(lo), "f"(hi)); return r;
}
__device__ __forceinline__ u64 splat2(float v) { return pack2(v, v); }
__device__ __forceinline__ u64 fma2(u64 a, u64 b, u64 c) {
    u64 d; asm("fma.rn.f32x2 %0,%1,%2,%3;" : "=l"(d) : "l"(a), "l"(b), "l"(c)); return d;
}
__device__ __forceinline__ void unpack2(u64 v, float& lo, float& hi) {
    asm("mov.b64 {%0,%1},%2;" : "=f"(lo), "=f"(hi) : "l"(v));
}
__device__ __forceinline__ float sigf(float x) {
    return __fdividef(1.f, 1.f + __expf(-x));
}
__device__ __forceinline__ float tanhfast(float x) {
    return __fdividef(2.f, 1.f + __expf(-2.f * x)) - 1.f;
}
__device__ __forceinline__ void cpasync16(uint32_t smem, const void* gmem) {
    asm volatile("cp.async.ca.shared.global [%0],[%1],16;" :: "r"(smem), "l"(gmem));
}
__device__ __forceinline__ void cpcommit() {
    asm volatile("cp.async.commit_group;");
}
__device__ __forceinline__ uint32_t smem_u32(const void* p) {
    uint32_t a;
    asm("{ .reg .u64 t; cvta.to.shared.u64 t, %1; cvt.u32.u64 %0, t; }" : "=r"(a) : "l"(p));
    return a;
}
__device__ __forceinline__ void split2h(float v, __half& h, __half& l) {
    h = __float2half_rn(v);
    l = __float2half_rn(v - __half2float(h));
}
#define LDSM4(d, addr) \
    asm volatile("ldmatrix.sync.aligned.m8n8.x4.shared.b16 {%0,%1,%2,%3},[%4];" \
        : "=r"((d)[0]), "=r"((d)[1]), "=r"((d)[2]), "=r"((d)[3]) : "r"(addr))
__device__ __forceinline__ void mma_f16(float* d, const uint32_t* a, uint32_t b0, uint32_t b1) {
    asm volatile(
        "mma.sync.aligned.m16n8k16.row.col.f32.f16.f16.f32 "
        "{%0,%1,%2,%3},{%4,%5,%6,%7},{%8,%9},{%0,%1,%2,%3};"
        : "+f"(d[0]), "+f"(d[1]), "+f"(d[2]), "+f"(d[3])
        : "r"(a[0]), "r"(a[1]), "r"(a[2]), "r"(a[3]), "r"(b0), "r"(b1));
}

// ---- device scratch ----
__device__ float g_M[Am*Cch*3];
__device__ float g_bias1[Cch];
__device__ __align__(128) __half g_wH[2*2*(size_t)G4*KPS];     // [dir*2+plane][g][k]
__device__ float g_whhT[2][Hm*G4];
__device__ float g_fcf[Tm*Hm];
__device__ float g_fcb[Tm*Hm];
__device__ float g_cbias[Tm];
__device__ __align__(128) __half g_featH[2*(size_t)Nt*KPS];    // [plane][n][k]
__device__ float g_gates[2][(size_t)Nt*G4];
__device__ float g_h[2][(size_t)Nt*Hm];
__device__ float g_emis[(size_t)Nt*Tm];

// ======================= prep kernels =======================
__global__ void prep_tables(const float* __restrict__ emb,
                            const float* __restrict__ conv_w,
                            const float* __restrict__ conv_b,
                            const float* __restrict__ g1,
                            const float* __restrict__ b1,
                            const float* __restrict__ m1,
                            const float* __restrict__ v1)
{
    int i = blockIdx.x*blockDim.x + threadIdx.x;
    if (i < Am*Cch*3) {
        int k = i % 3;
        int c = (i/3) % Cch;
        int a = i / (3*Cch);
        float s = 0.f;
        for (int e = 0; e < Em; e++)
            s += emb[a*Em + e] * conv_w[(c*Em + e)*3 + k];
        float sc = g1[c] * rsqrtf(v1[c] + 1e-5f);
        g_M[i] = s * sc;
    } else if (i < Am*Cch*3 + Cch) {
        int c = i - Am*Cch*3;
        float sc = g1[c] * rsqrtf(v1[c] + 1e-5f);
        g_bias1[c] = (conv_b[c] - m1[c]) * sc + b1[c];
    }
}

__global__ void prep_pack6(const float* __restrict__ wihf, const float* __restrict__ whhf,
                           const float* __restrict__ wihb, const float* __restrict__ whhb)
{
    int stride = gridDim.x * blockDim.x;
    int t0 = blockIdx.x*blockDim.x + threadIdx.x;
    for (int i = t0; i < G4*KPS; i += stride) {
        int g = i / KPS, k = i % KPS;
        float vf = (k < LIN) ? wihf[g*LIN + k] : 0.f;
        float vb = (k < LIN) ? wihb[g*LIN + k] : 0.f;
        __half h, l;
        split2h(vf, h, l);
        g_wH[(size_t)(0*2+0)*G4*KPS + i] = h;
        g_wH[(size_t)(0*2+1)*G4*KPS + i] = l;
        split2h(vb, h, l);
        g_wH[(size_t)(1*2+0)*G4*KPS + i] = h;
        g_wH[(size_t)(1*2+1)*G4*KPS + i] = l;
    }
    for (int i = t0; i < Hm*G4; i += stride) {
        int k = i / G4, g = i % G4;
        g_whhT[0][i] = whhf[g*Hm + k];
        g_whhT[1][i] = whhb[g*Hm + k];
    }
}

__global__ void prep_fc(const float* __restrict__ g2, const float* __restrict__ b2,
                        const float* __restrict__ m2, const float* __restrict__ v2,
                        const float* __restrict__ fcw, const float* __restrict__ fcbias)
{
    int t = threadIdx.x;
    if (t < Hm) {
        float s2a = g2[t]       * rsqrtf(v2[t]       + 1e-5f);
        float s2b = g2[Hm + t]  * rsqrtf(v2[Hm + t]  + 1e-5f);
        for (int tt = 0; tt < Tm; tt++) {
            g_fcf[tt*Hm + t] = fcw[tt*2*Hm + t]      * s2a;
            g_fcb[tt*Hm + t] = fcw[tt*2*Hm + Hm + t] * s2b;
        }
    }
    if (t < Tm) {
        float s = fcbias[t];
        for (int j = 0; j < 2*Hm; j++) {
            float s2 = g2[j] * rsqrtf(v2[j] + 1e-5f);
            s += (b2[j] - m2[j]*s2) * fcw[t*2*Hm + j];
        }
        g_cbias[t] = s;
    }
}

// ======================= fused featurize -> fp16 hi/lo planes =======================
// One thread per token: conv+bn+relu+pool for all 40 channels, split to fp16,
// coalesced-per-thread uint4 writes into [plane][n][k].
__global__ __launch_bounds__(128) void featfuse(const int* __restrict__ x)
{
    int n = blockIdx.x*128 + threadIdx.x;
    if (n >= Nt) return;
    int sym[Wm];
#pragma unroll
    for (int w = 0; w < Wm; w++) sym[w] = x[n*Wm + w];

    uint4* dh = (uint4*)(g_featH + (size_t)n*KPS);
    uint4* dl = (uint4*)(g_featH + (size_t)Nt*KPS + (size_t)n*KPS);

#pragma unroll
    for (int g = 0; g < 5; g++) {
        __align__(16) __half th[40];
        __align__(16) __half tl[40];
#pragma unroll
        for (int cc = 0; cc < 8; cc++) {
            int c = g*8 + cc;
            float bb = g_bias1[c];
            float y[Wm];
#pragma unroll
            for (int w = 0; w < Wm; w++) {
                float v = bb;
#pragma unroll
                for (int k = 0; k < 3; k++) {
                    int p = w + k - 1;
                    if (p >= 0 && p < Wm)
                        v += g_M[sym[p]*(Cch*3) + c*3 + k];
                }
                y[w] = fmaxf(v, 0.f);
            }
#pragma unroll
            for (int w = 0; w < Wm; w++) {
                float p = y[w];
                if (w > 0)      p = fmaxf(p, y[w-1]);
                if (w < Wm-1)   p = fmaxf(p, y[w+1]);
                __half h, l;
                split2h(p, h, l);
                th[cc*Wm + w] = h;
                tl[cc*Wm + w] = l;
            }
        }
        const uint4* sh = (const uint4*)th;
        const uint4* sl = (const uint4*)tl;
#pragma unroll
        for (int i = 0; i < 5; i++) {
            dh[g*5 + i] = sh[i];
            dl[g*5 + i] = sl[i];
        }
    }
    uint4 z = make_uint4(0, 0, 0, 0);
#pragma unroll
    for (int i = 25; i < 28; i++) { dh[i] = z; dl[i] = z; }
}

// ======================= input GEMM v10: fp16 2-plane split, k-chunk 32 =======================
// 128x128 block, 8 warps (wm=w&3 -> 32 M rows, wn=w>>2 -> 64 N cols).
// 3 split terms: ah*bh, al*bh, ah*bl. 7 chunks of k=32, double-buffered, 64KB dyn smem.
// Rows 64B (32 halves); swizzle: quad ^= (row>>1)&3 (conflict-free cp.async + LDSM).
__global__ __launch_bounds__(256, 2) void gemm_f16s(const float* __restrict__ bias_f,
                                                    const float* __restrict__ bias_b)
{
    extern __shared__ __align__(16) char dynsm[];
    uint32_t sbase = smem_u32(dynsm);

    int dir = blockIdx.x >> 2;
    int n0  = (blockIdx.x & 3) * 128;
    int m0  = blockIdx.y * 128;
    const float* __restrict__ bias = dir ? bias_b : bias_f;
    float* __restrict__ Co = g_gates[dir];

    int t = threadIdx.x, lane = t & 31, w = t >> 5;
    int wm = w & 3, wn = w >> 2;
    int gi = lane >> 2, li = lane & 3;

    // carve: A regions [buf][pl] 8KB each at 0..32KB, B at 32KB..64KB
    uint32_t aB[2][2], bB[2][2];
#pragma unroll
    for (int b = 0; b < 2; b++)
#pragma unroll
        for (int p = 0; p < 2; p++) {
            aB[b][p] = sbase + (uint32_t)((b*2 + p) * 8192);
            bB[b][p] = sbase + 32768u + (uint32_t)((b*2 + p) * 8192);
        }

    float acc[2][8][4];
#pragma unroll
    for (int mt = 0; mt < 2; mt++)
#pragma unroll
        for (int nt = 0; nt < 8; nt++)
#pragma unroll
            for (int q = 0; q < 4; q++) acc[mt][nt][q] = 0.f;

    int lrow = t >> 2;        // 0..63
    int lq   = t & 3;         // quad 0..3

    auto load_chunk = [&](int kc, int buf) {
        size_t go = (size_t)kc*32 + lq*8;
#pragma unroll
        for (int rr = 0; rr < 2; rr++) {
            int row = lrow + rr*64;
            uint32_t so = (uint32_t)(row*64 + ((lq ^ ((row >> 1) & 3)) << 4));
#pragma unroll
            for (int pl = 0; pl < 2; pl++) {
                cpasync16(aB[buf][pl] + so,
                          g_featH + ((size_t)pl*Nt + m0 + row)*KPS + go);
                cpasync16(bB[buf][pl] + so,
                          g_wH + ((size_t)(dir*2 + pl)*G4 + n0 + row)*KPS + go);
            }
        }
        cpcommit();
    };

    load_chunk(0, 0);

    int r15 = lane & 15;
    int qhi = lane >> 4;      // 0 or 1

    for (int c = 0; c < NCH; c++) {
        int buf = c & 1;
        if (c + 1 < NCH) {
            load_chunk(c + 1, buf ^ 1);
            asm volatile("cp.async.wait_group 1;");
        } else {
            asm volatile("cp.async.wait_group 0;");
        }
        __syncthreads();

#pragma unroll
        for (int kg = 0; kg < 2; kg++) {
            int qb = kg*2 + qhi;
            uint32_t bh[4][4], bl[4][4];
#pragma unroll
            for (int np = 0; np < 4; np++) {
                int row = wn*64 + np*16 + r15;
                uint32_t off = (uint32_t)(row*64 + ((qb ^ ((row >> 1) & 3)) << 4));
                LDSM4(bh[np], bB[buf][0] + off);
                LDSM4(bl[np], bB[buf][1] + off);
            }
            uint32_t ah0[4], ah1[4], al0[4], al1[4];
            {
                int row = wm*32 + r15;
                uint32_t off = (uint32_t)(row*64 + ((qb ^ ((row >> 1) & 3)) << 4));
                LDSM4(ah0, aB[buf][0] + off);
                LDSM4(al0, aB[buf][1] + off);
                row += 16;
                off = (uint32_t)(row*64 + ((qb ^ ((row >> 1) & 3)) << 4));
                LDSM4(ah1, aB[buf][0] + off);
                LDSM4(al1, aB[buf][1] + off);
            }
#pragma unroll
            for (int nt = 0; nt < 8; nt++) {
                uint32_t b0h = bh[nt >> 1][nt & 1];
                uint32_t b1h = bh[nt >> 1][2 + (nt & 1)];
                uint32_t b0l = bl[nt >> 1][nt & 1];
                uint32_t b1l = bl[nt >> 1][2 + (nt & 1)];
                mma_f16(acc[0][nt], ah0, b0h, b1h);
                mma_f16(acc[1][nt], ah1, b0h, b1h);
                mma_f16(acc[0][nt], al0, b0h, b1h);
                mma_f16(acc[1][nt], al1, b0h, b1h);
                mma_f16(acc[0][nt], ah0, b0l, b1l);
                mma_f16(acc[1][nt], ah1, b0l, b1l);
            }
        }
        __syncthreads();
    }

#pragma unroll
    for (int mt = 0; mt < 2; mt++) {
        size_t r0 = (size_t)(m0 + wm*32 + mt*16 + gi);
#pragma unroll
        for (int nt = 0; nt < 8; nt++) {
            int col = n0 + wn*64 + nt*8 + 2*li;
            float b0 = bias[col], b1 = bias[col + 1];
            float2 v;
            v.x = acc[mt][nt][0] + b0; v.y = acc[mt][nt][1] + b1;
            *(float2*)(Co + r0*G4 + col) = v;
            v.x = acc[mt][nt][2] + b0; v.y = acc[mt][nt][3] + b1;
            *(float2*)(Co + (r0 + 8)*G4 + col) = v;
        }
    }
}

// ======================= LSTM recurrence (both dirs fused, f32x2) =======================
__global__ __launch_bounds__(256, 2) void lstm_fused()
{
    int dir = blockIdx.x >> 7;
    int blk = blockIdx.x & 127;
    const float* __restrict__ gates = g_gates[dir];
    const float* __restrict__ whhT  = g_whhT[dir];
    float* __restrict__ hout        = g_h[dir];

    __shared__ __align__(16) float hs[2][Hm][36];

    int t = threadIdx.x;
    int j = t & 127;
    int half = t >> 7;
    int r0 = blk * 32 + half * 16;

    for (int i = t; i < 2*Hm*36; i += 256) ((float*)hs)[i] = 0.f;

    float cst[16];
#pragma unroll
    for (int r = 0; r < 16; r++) cst[r] = 0.f;
    __syncthreads();

    int cur = 0;
    const float* wp = whhT + j;

    for (int li = 0; li < Lm; li++) {
        int l = dir ? (Lm-1-li) : li;

        u64 acc2[4][8];
#pragma unroll
        for (int g = 0; g < 4; g++)
#pragma unroll
            for (int q = 0; q < 8; q++) {
                size_t base = ((size_t)(r0 + 2*q)*Lm + l)*G4 + g*128 + j;
                float lo = gates[base];
                float hi = gates[base + (size_t)Lm*G4];
                acc2[g][q] = pack2(lo, hi);
            }

#pragma unroll 4
        for (int k = 0; k < Hm; k++) {
            float w0 = wp[k*G4 + 0];
            float w1 = wp[k*G4 + 128];
            float w2 = wp[k*G4 + 256];
            float w3 = wp[k*G4 + 384];
            u64 w0p = splat2(w0), w1p = splat2(w1);
            u64 w2p = splat2(w2), w3p = splat2(w3);
            const ulonglong2* hp = (const ulonglong2*)&hs[cur][k][half*16];
#pragma unroll
            for (int qq = 0; qq < 4; qq++) {
                ulonglong2 hv2 = hp[qq];
                acc2[0][2*qq]   = fma2(w0p, hv2.x, acc2[0][2*qq]);
                acc2[1][2*qq]   = fma2(w1p, hv2.x, acc2[1][2*qq]);
                acc2[2][2*qq]   = fma2(w2p, hv2.x, acc2[2][2*qq]);
                acc2[3][2*qq]   = fma2(w3p, hv2.x, acc2[3][2*qq]);
                acc2[0][2*qq+1] = fma2(w0p, hv2.y, acc2[0][2*qq+1]);
                acc2[1][2*qq+1] = fma2(w1p, hv2.y, acc2[1][2*qq+1]);
                acc2[2][2*qq+1] = fma2(w2p, hv2.y, acc2[2][2*qq+1]);
                acc2[3][2*qq+1] = fma2(w3p, hv2.y, acc2[3][2*qq+1]);
            }
        }

#pragma unroll
        for (int q = 0; q < 8; q++) {
            float zi0,zi1,zf0,zf1,zg0,zg1,zo0,zo1;
            unpack2(acc2[0][q], zi0, zi1);
            unpack2(acc2[1][q], zf0, zf1);
            unpack2(acc2[2][q], zg0, zg1);
            unpack2(acc2[3][q], zo0, zo1);
            {
                float ig = sigf(zi0), fg = sigf(zf0);
                float gg = tanhfast(zg0), og = sigf(zo0);
                float cn = fg*cst[2*q] + ig*gg;
                cst[2*q] = cn;
                float hn = og * tanhfast(cn);
                hs[cur^1][j][half*16 + 2*q] = hn;
                hout[((size_t)(r0 + 2*q)*Lm + l)*Hm + j] = hn;
            }
            {
                float ig = sigf(zi1), fg = sigf(zf1);
                float gg = tanhfast(zg1), og = sigf(zo1);
                float cn = fg*cst[2*q+1] + ig*gg;
                cst[2*q+1] = cn;
                float hn = og * tanhfast(cn);
                hs[cur^1][j][half*16 + 2*q + 1] = hn;
                hout[((size_t)(r0 + 2*q + 1)*Lm + l)*Hm + j] = hn;
            }
        }
        cur ^= 1;
        __syncthreads();
    }
}

// ======================= emission (BN2+FC folded) =======================
__global__ void emission_kernel()
{
    int gt = blockIdx.x*blockDim.x + threadIdx.x;
    int warp = gt >> 5;
    int lane = threadIdx.x & 31;
    if (warp >= Nt) return;
    float4 hf4 = *(const float4*)&g_h[0][(size_t)warp*Hm + lane*4];
    float4 hb4 = *(const float4*)&g_h[1][(size_t)warp*Hm + lane*4];
#pragma unroll
    for (int tt = 0; tt < Tm; tt++) {
        float4 f4 = *(const float4*)&g_fcf[tt*Hm + lane*4];
        float4 b4 = *(const float4*)&g_fcb[tt*Hm + lane*4];
        float s = hf4.x*f4.x + hf4.y*f4.y + hf4.z*f4.z + hf4.w*f4.w
                + hb4.x*b4.x + hb4.y*b4.y + hb4.z*b4.z + hb4.w*b4.w;
#pragma unroll
        for (int o = 16; o; o >>= 1) s += __shfl_xor_sync(0xffffffffu, s, o);
        if (lane == 0) g_emis[(size_t)warp*Tm + tt] = s + g_cbias[tt];
    }
}

// ======================= Viterbi =======================
__global__ void viterbi_kernel(const int* __restrict__ x,
                               const float* __restrict__ trans,
                               const float* __restrict__ start_t,
                               const float* __restrict__ end_t,
                               float* __restrict__ out)
{
    int b = blockIdx.x*blockDim.x + threadIdx.x;
    if (b >= Bsz) return;
    float tr[9];
#pragma unroll
    for (int i = 0; i < 9; i++) tr[i] = trans[i];
    const float* em = g_emis + (size_t)b*Lm*Tm;
    float sc[3];
#pragma unroll
    for (int t = 0; t < 3; t++) sc[t] = start_t[t] + em[t];

    unsigned char hist[Lm-1][3];
    for (int l = 1; l < Lm; l++) {
        bool m = x[(b*Lm + l)*Wm + 2] > 0;
        float ns[3];
#pragma unroll
        for (int t = 0; t < 3; t++) {
            float best = sc[0] + tr[0*3 + t];
            int bp = 0;
#pragma unroll
            for (int p = 1; p < 3; p++) {
                float v = sc[p] + tr[p*3 + t];
                if (v > best) { best = v; bp = p; }
            }
            hist[l-1][t] = (unsigned char)bp;
            ns[t] = best + em[l*Tm + t];
        }
        if (m) { sc[0]=ns[0]; sc[1]=ns[1]; sc[2]=ns[2]; }
    }
#pragma unroll
    for (int t = 0; t < 3; t++) sc[t] += end_t[t];
    float best = sc[0]; int last = 0;
    if (sc[1] > best) { best = sc[1]; last = 1; }
    if (sc[2] > best) { best = sc[2]; last = 2; }
    out[b] = best;

    float* tagout = out + Bsz;
    int tag = last;
    tagout[(size_t)b*Lm + (Lm-1)] = (float)tag;
    for (int i = Lm-2; i >= 0; i--) {
        int prev = hist[i][tag];
        bool m = x[(b*Lm + i + 1)*Wm + 2] > 0;
        if (m) tag = prev;
        tagout[(size_t)b*Lm + i] = (float)tag;
    }
}

// ======================= launch =======================
extern "C" void kernel_launch(void* const* d_in, const int* in_sizes, int n_in,
                              void* d_out, int out_size)
{
    (void)in_sizes; (void)n_in; (void)out_size;
    const int*   x      = (const int*)  d_in[0];
    const float* emb    = (const float*)d_in[1];
    const float* conv_w = (const float*)d_in[2];
    const float* conv_b = (const float*)d_in[3];
    const float* bn1_g  = (const float*)d_in[4];
    const float* bn1_b  = (const float*)d_in[5];
    const float* bn1_m  = (const float*)d_in[6];
    const float* bn1_v  = (const float*)d_in[7];
    const float* w_ih_f = (const float*)d_in[8];
    const float* w_hh_f = (const float*)d_in[9];
    const float* b_f    = (const float*)d_in[10];
    const float* w_ih_b = (const float*)d_in[11];
    const float* w_hh_b = (const float*)d_in[12];
    const float* b_b    = (const float*)d_in[13];
    const float* bn2_g  = (const float*)d_in[14];
    const float* bn2_b  = (const float*)d_in[15];
    const float* bn2_m  = (const float*)d_in[16];
    const float* bn2_v  = (const float*)d_in[17];
    const float* fc_w   = (const float*)d_in[18];
    const float* fc_b   = (const float*)d_in[19];
    const float* trans  = (const float*)d_in[20];
    const float* start_t= (const float*)d_in[21];
    const float* end_t  = (const float*)d_in[22];
    float* out = (float*)d_out;

    cudaFuncSetAttribute(gemm_f16s, cudaFuncAttributeMaxDynamicSharedMemorySize, 65536);

    prep_tables<<<(Am*Cch*3 + Cch + 255)/256, 256>>>(emb, conv_w, conv_b,
                                                     bn1_g, bn1_b, bn1_m, bn1_v);
    prep_pack6<<<512, 256>>>(w_ih_f, w_hh_f, w_ih_b, w_hh_b);
    prep_fc<<<1, 256>>>(bn2_g, bn2_b, bn2_m, bn2_v, fc_w, fc_b);

    featfuse<<<Nt/128, 128>>>(x);

    dim3 gg(8, Nt/128);
    gemm_f16s<<<gg, 256, 65536>>>(b_f, b_b);

    lstm_fused<<<256, 256>>>();

    emission_kernel<<<(Nt + 3)/4, 128>>>();

    viterbi_kernel<<<(Bsz + 127)/128, 128>>>(x, trans, start_t, end_t, out);
}

// round 13
// speedup vs baseline: 1.5859x; 1.2279x over previous
#include <cuda_runtime.h>
#include <cuda_fp16.h>
#include <math.h>
#include <stdint.h>

// ---- problem constants ----
#define Bsz 4096
#define Lm  30
#define Wm  5
#define Am  30
#define Em  128
#define Cch 40
#define Hm  128
#define Tm  3
#define LIN 200
#define KPS 224          // padded K stride for fp16 planes (7 x 32)
#define Nt  (Bsz*Lm)     // 122880 tokens
#define G4  512          // 4*H gates
#define NCH 7            // 224/32 k-chunks

typedef unsigned long long u64;

__device__ __forceinline__ float sigf(float x) {
    return __fdividef(1.f, 1.f + __expf(-x));
}
__device__ __forceinline__ float tanhfast(float x) {
    return __fdividef(2.f, 1.f + __expf(-2.f * x)) - 1.f;
}
__device__ __forceinline__ void cpasync16(uint32_t smem, const void* gmem) {
    asm volatile("cp.async.ca.shared.global [%0],[%1],16;" :: "r"(smem), "l"(gmem));
}
__device__ __forceinline__ void cpcommit() {
    asm volatile("cp.async.commit_group;");
}
__device__ __forceinline__ uint32_t smem_u32(const void* p) {
    uint32_t a;
    asm("{ .reg .u64 t; cvta.to.shared.u64 t, %1; cvt.u32.u64 %0, t; }" : "=r"(a) : "l"(p));
    return a;
}
__device__ __forceinline__ void split2h(float v, __half& h, __half& l) {
    h = __float2half_rn(v);
    l = __float2half_rn(v - __half2float(h));
}
#define LDSM4(d, addr) \
    asm volatile("ldmatrix.sync.aligned.m8n8.x4.shared.b16 {%0,%1,%2,%3},[%4];" \
        : "=r"((d)[0]), "=r"((d)[1]), "=r"((d)[2]), "=r"((d)[3]) : "r"(addr))
__device__ __forceinline__ void mma_f16(float* d, const uint32_t* a, uint32_t b0, uint32_t b1) {
    asm volatile(
        "mma.sync.aligned.m16n8k16.row.col.f32.f16.f16.f32 "
        "{%0,%1,%2,%3},{%4,%5,%6,%7},{%8,%9},{%0,%1,%2,%3};"
        : "+f"(d[0]), "+f"(d[1]), "+f"(d[2]), "+f"(d[3])
        : "r"(a[0]), "r"(a[1]), "r"(a[2]), "r"(a[3]), "r"(b0), "r"(b1));
}

// ---- device scratch ----
__device__ float g_M[Am*Cch*3];
__device__ float g_bias1[Cch];
__device__ __align__(128) __half g_wH[2*2*(size_t)G4*KPS];     // input weights [dir*2+plane][g][k]
__device__ __align__(128) __half g_wHH[2*2*(size_t)G4*Hm];     // recurrent [dir][pl][512][128]
__device__ float g_fcf[Tm*Hm];
__device__ float g_fcb[Tm*Hm];
__device__ float g_cbias[Tm];
__device__ __align__(128) __half g_featH[2*(size_t)Nt*KPS];    // [plane][n][k]
__device__ float g_gates[2][(size_t)Nt*G4];
__device__ float g_h[2][(size_t)Nt*Hm];
__device__ float g_emis[(size_t)Nt*Tm];

// ======================= prep kernels =======================
__global__ void prep_tables(const float* __restrict__ emb,
                            const float* __restrict__ conv_w,
                            const float* __restrict__ conv_b,
                            const float* __restrict__ g1,
                            const float* __restrict__ b1,
                            const float* __restrict__ m1,
                            const float* __restrict__ v1)
{
    int i = blockIdx.x*blockDim.x + threadIdx.x;
    if (i < Am*Cch*3) {
        int k = i % 3;
        int c = (i/3) % Cch;
        int a = i / (3*Cch);
        float s = 0.f;
        for (int e = 0; e < Em; e++)
            s += emb[a*Em + e] * conv_w[(c*Em + e)*3 + k];
        float sc = g1[c] * rsqrtf(v1[c] + 1e-5f);
        g_M[i] = s * sc;
    } else if (i < Am*Cch*3 + Cch) {
        int c = i - Am*Cch*3;
        float sc = g1[c] * rsqrtf(v1[c] + 1e-5f);
        g_bias1[c] = (conv_b[c] - m1[c]) * sc + b1[c];
    }
}

__global__ void prep_pack7(const float* __restrict__ wihf, const float* __restrict__ whhf,
                           const float* __restrict__ wihb, const float* __restrict__ whhb)
{
    int stride = gridDim.x * blockDim.x;
    int t0 = blockIdx.x*blockDim.x + threadIdx.x;
    for (int i = t0; i < G4*KPS; i += stride) {
        int g = i / KPS, k = i % KPS;
        float vf = (k < LIN) ? wihf[g*LIN + k] : 0.f;
        float vb = (k < LIN) ? wihb[g*LIN + k] : 0.f;
        __half h, l;
        split2h(vf, h, l);
        g_wH[(size_t)(0*2+0)*G4*KPS + i] = h;
        g_wH[(size_t)(0*2+1)*G4*KPS + i] = l;
        split2h(vb, h, l);
        g_wH[(size_t)(1*2+0)*G4*KPS + i] = h;
        g_wH[(size_t)(1*2+1)*G4*KPS + i] = l;
    }
    // recurrent weights: [512][128] row-major directly
    for (int i = t0; i < G4*Hm; i += stride) {
        __half h, l;
        split2h(whhf[i], h, l);
        g_wHH[(size_t)(0*2+0)*G4*Hm + i] = h;
        g_wHH[(size_t)(0*2+1)*G4*Hm + i] = l;
        split2h(whhb[i], h, l);
        g_wHH[(size_t)(1*2+0)*G4*Hm + i] = h;
        g_wHH[(size_t)(1*2+1)*G4*Hm + i] = l;
    }
}

__global__ void prep_fc(const float* __restrict__ g2, const float* __restrict__ b2,
                        const float* __restrict__ m2, const float* __restrict__ v2,
                        const float* __restrict__ fcw, const float* __restrict__ fcbias)
{
    int t = threadIdx.x;
    if (t < Hm) {
        float s2a = g2[t]       * rsqrtf(v2[t]       + 1e-5f);
        float s2b = g2[Hm + t]  * rsqrtf(v2[Hm + t]  + 1e-5f);
        for (int tt = 0; tt < Tm; tt++) {
            g_fcf[tt*Hm + t] = fcw[tt*2*Hm + t]      * s2a;
            g_fcb[tt*Hm + t] = fcw[tt*2*Hm + Hm + t] * s2b;
        }
    }
    if (t < Tm) {
        float s = fcbias[t];
        for (int j = 0; j < 2*Hm; j++) {
            float s2 = g2[j] * rsqrtf(v2[j] + 1e-5f);
            s += (b2[j] - m2[j]*s2) * fcw[t*2*Hm + j];
        }
        g_cbias[t] = s;
    }
}

// ======================= fused featurize -> fp16 hi/lo planes =======================
__global__ __launch_bounds__(128) void featfuse(const int* __restrict__ x)
{
    int n = blockIdx.x*128 + threadIdx.x;
    if (n >= Nt) return;
    int sym[Wm];
#pragma unroll
    for (int w = 0; w < Wm; w++) sym[w] = x[n*Wm + w];

    uint4* dh = (uint4*)(g_featH + (size_t)n*KPS);
    uint4* dl = (uint4*)(g_featH + (size_t)Nt*KPS + (size_t)n*KPS);

#pragma unroll
    for (int g = 0; g < 5; g++) {
        __align__(16) __half th[40];
        __align__(16) __half tl[40];
#pragma unroll
        for (int cc = 0; cc < 8; cc++) {
            int c = g*8 + cc;
            float bb = g_bias1[c];
            float y[Wm];
#pragma unroll
            for (int w = 0; w < Wm; w++) {
                float v = bb;
#pragma unroll
                for (int k = 0; k < 3; k++) {
                    int p = w + k - 1;
                    if (p >= 0 && p < Wm)
                        v += g_M[sym[p]*(Cch*3) + c*3 + k];
                }
                y[w] = fmaxf(v, 0.f);
            }
#pragma unroll
            for (int w = 0; w < Wm; w++) {
                float p = y[w];
                if (w > 0)      p = fmaxf(p, y[w-1]);
                if (w < Wm-1)   p = fmaxf(p, y[w+1]);
                __half h, l;
                split2h(p, h, l);
                th[cc*Wm + w] = h;
                tl[cc*Wm + w] = l;
            }
        }
        const uint4* sh = (const uint4*)th;
        const uint4* sl = (const uint4*)tl;
#pragma unroll
        for (int i = 0; i < 5; i++) {
            dh[g*5 + i] = sh[i];
            dl[g*5 + i] = sl[i];
        }
    }
    uint4 z = make_uint4(0, 0, 0, 0);
#pragma unroll
    for (int i = 25; i < 28; i++) { dh[i] = z; dl[i] = z; }
}

// ======================= input GEMM (unchanged from R11) =======================
__global__ __launch_bounds__(256, 2) void gemm_f16s(const float* __restrict__ bias_f,
                                                    const float* __restrict__ bias_b)
{
    extern __shared__ __align__(16) char dynsm[];
    uint32_t sbase = smem_u32(dynsm);

    int dir = blockIdx.x >> 2;
    int n0  = (blockIdx.x & 3) * 128;
    int m0  = blockIdx.y * 128;
    const float* __restrict__ bias = dir ? bias_b : bias_f;
    float* __restrict__ Co = g_gates[dir];

    int t = threadIdx.x, lane = t & 31, w = t >> 5;
    int wm = w & 3, wn = w >> 2;
    int gi = lane >> 2, li = lane & 3;

    uint32_t aB[2][2], bB[2][2];
#pragma unroll
    for (int b = 0; b < 2; b++)
#pragma unroll
        for (int p = 0; p < 2; p++) {
            aB[b][p] = sbase + (uint32_t)((b*2 + p) * 8192);
            bB[b][p] = sbase + 32768u + (uint32_t)((b*2 + p) * 8192);
        }

    float acc[2][8][4];
#pragma unroll
    for (int mt = 0; mt < 2; mt++)
#pragma unroll
        for (int nt = 0; nt < 8; nt++)
#pragma unroll
            for (int q = 0; q < 4; q++) acc[mt][nt][q] = 0.f;

    int lrow = t >> 2;
    int lq   = t & 3;

    auto load_chunk = [&](int kc, int buf) {
        size_t go = (size_t)kc*32 + lq*8;
#pragma unroll
        for (int rr = 0; rr < 2; rr++) {
            int row = lrow + rr*64;
            uint32_t so = (uint32_t)(row*64 + ((lq ^ ((row >> 1) & 3)) << 4));
#pragma unroll
            for (int pl = 0; pl < 2; pl++) {
                cpasync16(aB[buf][pl] + so,
                          g_featH + ((size_t)pl*Nt + m0 + row)*KPS + go);
                cpasync16(bB[buf][pl] + so,
                          g_wH + ((size_t)(dir*2 + pl)*G4 + n0 + row)*KPS + go);
            }
        }
        cpcommit();
    };

    load_chunk(0, 0);

    int r15 = lane & 15;
    int qhi = lane >> 4;

    for (int c = 0; c < NCH; c++) {
        int buf = c & 1;
        if (c + 1 < NCH) {
            load_chunk(c + 1, buf ^ 1);
            asm volatile("cp.async.wait_group 1;");
        } else {
            asm volatile("cp.async.wait_group 0;");
        }
        __syncthreads();

#pragma unroll
        for (int kg = 0; kg < 2; kg++) {
            int qb = kg*2 + qhi;
            uint32_t bh[4][4], bl[4][4];
#pragma unroll
            for (int np = 0; np < 4; np++) {
                int row = wn*64 + np*16 + r15;
                uint32_t off = (uint32_t)(row*64 + ((qb ^ ((row >> 1) & 3)) << 4));
                LDSM4(bh[np], bB[buf][0] + off);
                LDSM4(bl[np], bB[buf][1] + off);
            }
            uint32_t ah0[4], ah1[4], al0[4], al1[4];
            {
                int row = wm*32 + r15;
                uint32_t off = (uint32_t)(row*64 + ((qb ^ ((row >> 1) & 3)) << 4));
                LDSM4(ah0, aB[buf][0] + off);
                LDSM4(al0, aB[buf][1] + off);
                row += 16;
                off = (uint32_t)(row*64 + ((qb ^ ((row >> 1) & 3)) << 4));
                LDSM4(ah1, aB[buf][0] + off);
                LDSM4(al1, aB[buf][1] + off);
            }
#pragma unroll
            for (int nt = 0; nt < 8; nt++) {
                uint32_t b0h = bh[nt >> 1][nt & 1];
                uint32_t b1h = bh[nt >> 1][2 + (nt & 1)];
                uint32_t b0l = bl[nt >> 1][nt & 1];
                uint32_t b1l = bl[nt >> 1][2 + (nt & 1)];
                mma_f16(acc[0][nt], ah0, b0h, b1h);
                mma_f16(acc[1][nt], ah1, b0h, b1h);
                mma_f16(acc[0][nt], al0, b0h, b1h);
                mma_f16(acc[1][nt], al1, b0h, b1h);
                mma_f16(acc[0][nt], ah0, b0l, b1l);
                mma_f16(acc[1][nt], ah1, b0l, b1l);
            }
        }
        __syncthreads();
    }

#pragma unroll
    for (int mt = 0; mt < 2; mt++) {
        size_t r0 = (size_t)(m0 + wm*32 + mt*16 + gi);
#pragma unroll
        for (int nt = 0; nt < 8; nt++) {
            int col = n0 + wn*64 + nt*8 + 2*li;
            float b0 = bias[col], b1 = bias[col + 1];
            float2 v;
            v.x = acc[mt][nt][0] + b0; v.y = acc[mt][nt][1] + b1;
            *(float2*)(Co + r0*G4 + col) = v;
            v.x = acc[mt][nt][2] + b0; v.y = acc[mt][nt][3] + b1;
            *(float2*)(Co + (r0 + 8)*G4 + col) = v;
        }
    }
}

// ======================= tensor-core LSTM =======================
// Block = 64 batch rows x 1 dir; 256 threads (8 warps), warp w owns j-slice [w*16, w*16+16).
// Per step: Z = H(fp16 hi/lo) @ WhhT (fp16 hi/lo, 3 terms) via mma; Whh streamed in
// four 64KB k-quarters (2-slot cp.async ring); h in smem (256B rows, xor row&15 swizzle);
// c in padded smem. Dyn smem: W 131072 + h 32768 + c 33792 = 197632.
#define LTC_WOFF 0
#define LTC_HOFF 131072
#define LTC_COFF 163840
#define LTC_SMEM 197632
__global__ __launch_bounds__(256, 1) void lstm_tc()
{
    extern __shared__ __align__(16) char dynsm[];
    uint32_t sb = smem_u32(dynsm);
    float* cs = (float*)(dynsm + LTC_COFF);

    int t = threadIdx.x, lane = t & 31, w = t >> 5;
    int gi = lane >> 2, li = lane & 3;
    int r15 = lane & 15, qhi = lane >> 4;
    int dir = blockIdx.x & 1;
    int rb0 = (blockIdx.x >> 1) * 64;
    const float* __restrict__ gates = g_gates[dir];
    float* __restrict__ hout = g_h[dir];
    const __half* __restrict__ Wg = g_wHH + (size_t)dir*2*G4*Hm;

    // init h smem (2 planes x 64 x 256B) and c smem to zero
    for (int i = t; i < 32768/4; i += 256) ((uint32_t*)(dynsm + LTC_HOFF))[i] = 0u;
    for (int i = t; i < 33792/4; i += 256) ((uint32_t*)(dynsm + LTC_COFF))[i] = 0u;

    // quarter loader: quarter qt (k-range qt*32..+32), slot s
    auto load_quarter = [&](int qt, int s) {
        uint32_t base = sb + LTC_WOFF + (uint32_t)s*65536;
#pragma unroll
        for (int pl = 0; pl < 2; pl++) {
            const __half* src = Wg + (size_t)pl*G4*Hm + qt*32;
#pragma unroll
            for (int i = 0; i < 8; i++) {
                int idx = i*256 + t;
                int row = idx >> 2, q4 = idx & 3;
                cpasync16(base + (uint32_t)(pl*32768 + row*64 + ((q4 ^ (row & 3)) << 4)),
                          src + (size_t)row*Hm + q4*8);
            }
        }
        cpcommit();
    };

    __syncthreads();
    load_quarter(0, 0);

    int qg = 0;   // global quarter counter
    for (int st = 0; st < Lm; st++) {
        int l = dir ? (Lm-1-st) : st;

        float acc[4][8][4];
#pragma unroll
        for (int mt = 0; mt < 4; mt++)
#pragma unroll
            for (int nt = 0; nt < 8; nt++)
#pragma unroll
                for (int e = 0; e < 4; e++) acc[mt][nt][e] = 0.f;

        for (int q = 0; q < 4; q++) {
            int slot = qg & 1;
            bool last = (st == Lm-1) && (q == 3);
            if (!last) {
                load_quarter((q + 1) & 3, (qg + 1) & 1);
                asm volatile("cp.async.wait_group 1;");
            } else {
                asm volatile("cp.async.wait_group 0;");
            }
            __syncthreads();

            uint32_t wbase = sb + LTC_WOFF + (uint32_t)slot*65536;
#pragma unroll
            for (int kgl = 0; kgl < 2; kgl++) {
                int chB = kgl*2 + qhi;
                uint32_t bh[4][4], bl[4][4];
#pragma unroll
                for (int g = 0; g < 4; g++) {
                    int rowB = g*128 + w*16 + r15;
                    uint32_t off = (uint32_t)(rowB*64 + ((chB ^ (rowB & 3)) << 4));
                    LDSM4(bh[g], wbase + off);
                    LDSM4(bl[g], wbase + 32768u + off);
                }
                int chA = q*4 + kgl*2 + qhi;
                uint32_t af[4][4];
#pragma unroll
                for (int mt = 0; mt < 4; mt++) {
                    int row = mt*16 + r15;
                    LDSM4(af[mt], sb + LTC_HOFF +
                          (uint32_t)(row*256 + ((chA ^ (row & 15)) << 4)));
                }
#pragma unroll
                for (int mt = 0; mt < 4; mt++)
#pragma unroll
                    for (int nt = 0; nt < 8; nt++) {
                        int g = nt >> 1, jt = nt & 1;
                        mma_f16(acc[mt][nt], af[mt], bh[g][jt], bh[g][2+jt]);
                        mma_f16(acc[mt][nt], af[mt], bl[g][jt], bl[g][2+jt]);
                    }
#pragma unroll
                for (int mt = 0; mt < 4; mt++) {
                    int row = mt*16 + r15;
                    LDSM4(af[mt], sb + LTC_HOFF + 16384u +
                          (uint32_t)(row*256 + ((chA ^ (row & 15)) << 4)));
                }
#pragma unroll
                for (int mt = 0; mt < 4; mt++)
#pragma unroll
                    for (int nt = 0; nt < 8; nt++) {
                        int g = nt >> 1, jt = nt & 1;
                        mma_f16(acc[mt][nt], af[mt], bh[g][jt], bh[g][2+jt]);
                    }
            }
            __syncthreads();
            qg++;
        }

        // epilogue: z = acc + input gates; activations; update c, h
#pragma unroll
        for (int mt = 0; mt < 4; mt++) {
#pragma unroll
            for (int rsel = 0; rsel < 2; rsel++) {
                int row = mt*16 + gi + rsel*8;
                const float* gp = gates + ((size_t)(rb0 + row)*Lm + l)*G4 + w*16 + 2*li;
#pragma unroll
                for (int jt = 0; jt < 2; jt++) {
                    float2 vi = *(const float2*)(gp + jt*8 + 0*128);
                    float2 vf = *(const float2*)(gp + jt*8 + 1*128);
                    float2 vg = *(const float2*)(gp + jt*8 + 2*128);
                    float2 vo = *(const float2*)(gp + jt*8 + 3*128);
                    int j0 = w*16 + jt*8 + 2*li;
                    float hn2[2];
#pragma unroll
                    for (int cc = 0; cc < 2; cc++) {
                        float zi = acc[mt][0*2+jt][rsel*2+cc] + (cc ? vi.y : vi.x);
                        float zf = acc[mt][1*2+jt][rsel*2+cc] + (cc ? vf.y : vf.x);
                        float zg = acc[mt][2*2+jt][rsel*2+cc] + (cc ? vg.y : vg.x);
                        float zo = acc[mt][3*2+jt][rsel*2+cc] + (cc ? vo.y : vo.x);
                        float ig = sigf(zi), fg = sigf(zf);
                        float gg = tanhfast(zg), og = sigf(zo);
                        float cp = cs[row*132 + j0 + cc];
                        float cn = fg*cp + ig*gg;
                        cs[row*132 + j0 + cc] = cn;
                        float hn = og * tanhfast(cn);
                        hn2[cc] = hn;
                        hout[((size_t)(rb0 + row)*Lm + l)*Hm + j0 + cc] = hn;
                    }
                    __half h0, l0, h1, l1;
                    split2h(hn2[0], h0, l0);
                    split2h(hn2[1], h1, l1);
                    int chunk = j0 >> 3;
                    uint32_t ho = (uint32_t)(row*256 + ((chunk ^ (row & 15)) << 4) + (j0 & 7)*2);
                    *(__half2*)(dynsm + LTC_HOFF + ho) = __halves2half2(h0, h1);
                    *(__half2*)(dynsm + LTC_HOFF + 16384 + ho) = __halves2half2(l0, l1);
                }
            }
        }
        __syncthreads();
    }
}

// ======================= emission (BN2+FC folded) =======================
__global__ void emission_kernel()
{
    int gt = blockIdx.x*blockDim.x + threadIdx.x;
    int warp = gt >> 5;
    int lane = threadIdx.x & 31;
    if (warp >= Nt) return;
    float4 hf4 = *(const float4*)&g_h[0][(size_t)warp*Hm + lane*4];
    float4 hb4 = *(const float4*)&g_h[1][(size_t)warp*Hm + lane*4];
#pragma unroll
    for (int tt = 0; tt < Tm; tt++) {
        float4 f4 = *(const float4*)&g_fcf[tt*Hm + lane*4];
        float4 b4 = *(const float4*)&g_fcb[tt*Hm + lane*4];
        float s = hf4.x*f4.x + hf4.y*f4.y + hf4.z*f4.z + hf4.w*f4.w
                + hb4.x*b4.x + hb4.y*b4.y + hb4.z*b4.z + hb4.w*b4.w;
#pragma unroll
        for (int o = 16; o; o >>= 1) s += __shfl_xor_sync(0xffffffffu, s, o);
        if (lane == 0) g_emis[(size_t)warp*Tm + tt] = s + g_cbias[tt];
    }
}

// ======================= Viterbi =======================
__global__ void viterbi_kernel(const int* __restrict__ x,
                               const float* __restrict__ trans,
                               const float* __restrict__ start_t,
                               const float* __restrict__ end_t,
                               float* __restrict__ out)
{
    int b = blockIdx.x*blockDim.x + threadIdx.x;
    if (b >= Bsz) return;
    float tr[9];
#pragma unroll
    for (int i = 0; i < 9; i++) tr[i] = trans[i];
    const float* em = g_emis + (size_t)b*Lm*Tm;
    float sc[3];
#pragma unroll
    for (int t = 0; t < 3; t++) sc[t] = start_t[t] + em[t];

    unsigned char hist[Lm-1][3];
    for (int l = 1; l < Lm; l++) {
        bool m = x[(b*Lm + l)*Wm + 2] > 0;
        float ns[3];
#pragma unroll
        for (int t = 0; t < 3; t++) {
            float best = sc[0] + tr[0*3 + t];
            int bp = 0;
#pragma unroll
            for (int p = 1; p < 3; p++) {
                float v = sc[p] + tr[p*3 + t];
                if (v > best) { best = v; bp = p; }
            }
            hist[l-1][t] = (unsigned char)bp;
            ns[t] = best + em[l*Tm + t];
        }
        if (m) { sc[0]=ns[0]; sc[1]=ns[1]; sc[2]=ns[2]; }
    }
#pragma unroll
    for (int t = 0; t < 3; t++) sc[t] += end_t[t];
    float best = sc[0]; int last = 0;
    if (sc[1] > best) { best = sc[1]; last = 1; }
    if (sc[2] > best) { best = sc[2]; last = 2; }
    out[b] = best;

    float* tagout = out + Bsz;
    int tag = last;
    tagout[(size_t)b*Lm + (Lm-1)] = (float)tag;
    for (int i = Lm-2; i >= 0; i--) {
        int prev = hist[i][tag];
        bool m = x[(b*Lm + i + 1)*Wm + 2] > 0;
        if (m) tag = prev;
        tagout[(size_t)b*Lm + i] = (float)tag;
    }
}

// ======================= launch =======================
extern "C" void kernel_launch(void* const* d_in, const int* in_sizes, int n_in,
                              void* d_out, int out_size)
{
    (void)in_sizes; (void)n_in; (void)out_size;
    const int*   x      = (const int*)  d_in[0];
    const float* emb    = (const float*)d_in[1];
    const float* conv_w = (const float*)d_in[2];
    const float* conv_b = (const float*)d_in[3];
    const float* bn1_g  = (const float*)d_in[4];
    const float* bn1_b  = (const float*)d_in[5];
    const float* bn1_m  = (const float*)d_in[6];
    const float* bn1_v  = (const float*)d_in[7];
    const float* w_ih_f = (const float*)d_in[8];
    const float* w_hh_f = (const float*)d_in[9];
    const float* b_f    = (const float*)d_in[10];
    const float* w_ih_b = (const float*)d_in[11];
    const float* w_hh_b = (const float*)d_in[12];
    const float* b_b    = (const float*)d_in[13];
    const float* bn2_g  = (const float*)d_in[14];
    const float* bn2_b  = (const float*)d_in[15];
    const float* bn2_m  = (const float*)d_in[16];
    const float* bn2_v  = (const float*)d_in[17];
    const float* fc_w   = (const float*)d_in[18];
    const float* fc_b   = (const float*)d_in[19];
    const float* trans  = (const float*)d_in[20];
    const float* start_t= (const float*)d_in[21];
    const float* end_t  = (const float*)d_in[22];
    float* out = (float*)d_out;

    cudaFuncSetAttribute(gemm_f16s, cudaFuncAttributeMaxDynamicSharedMemorySize, 65536);
    cudaFuncSetAttribute(lstm_tc, cudaFuncAttributeMaxDynamicSharedMemorySize, LTC_SMEM);

    prep_tables<<<(Am*Cch*3 + Cch + 255)/256, 256>>>(emb, conv_w, conv_b,
                                                     bn1_g, bn1_b, bn1_m, bn1_v);
    prep_pack7<<<512, 256>>>(w_ih_f, w_hh_f, w_ih_b, w_hh_b);
    prep_fc<<<1, 256>>>(bn2_g, bn2_b, bn2_m, bn2_v, fc_w, fc_b);

    featfuse<<<Nt/128, 128>>>(x);

    dim3 gg(8, Nt/128);
    gemm_f16s<<<gg, 256, 65536>>>(b_f, b_b);

    lstm_tc<<<128, 256, LTC_SMEM>>>();

    emission_kernel<<<(Nt + 3)/4, 128>>>();

    viterbi_kernel<<<(Bsz + 127)/128, 128>>>(x, trans, start_t, end_t, out);
}

// round 14
// speedup vs baseline: 1.6339x; 1.0302x over previous
#include <cuda_runtime.h>
#include <cuda_fp16.h>
#include <math.h>
#include <stdint.h>

// ---- problem constants ----
#define Bsz 4096
#define Lm  30
#define Wm  5
#define Am  30
#define Em  128
#define Cch 40
#define Hm  128
#define Tm  3
#define LIN 200
#define KPS 224          // padded K stride for fp16 planes (7 x 32)
#define Nt  (Bsz*Lm)     // 122880 tokens
#define G4  512          // 4*H gates
#define NCH 7            // 224/32 k-chunks

typedef unsigned long long u64;

__device__ __forceinline__ float sigf(float x) {
    return __fdividef(1.f, 1.f + __expf(-x));
}
__device__ __forceinline__ float tanhfast(float x) {
    return __fdividef(2.f, 1.f + __expf(-2.f * x)) - 1.f;
}
__device__ __forceinline__ void cpasync16(uint32_t smem, const void* gmem) {
    asm volatile("cp.async.ca.shared.global [%0],[%1],16;" :: "r"(smem), "l"(gmem));
}
__device__ __forceinline__ void cpcommit() {
    asm volatile("cp.async.commit_group;");
}
__device__ __forceinline__ uint32_t smem_u32(const void* p) {
    uint32_t a;
    asm("{ .reg .u64 t; cvta.to.shared.u64 t, %1; cvt.u32.u64 %0, t; }" : "=r"(a) : "l"(p));
    return a;
}
__device__ __forceinline__ void split2h(float v, __half& h, __half& l) {
    h = __float2half_rn(v);
    l = __float2half_rn(v - __half2float(h));
}
#define LDSM4(d, addr) \
    asm volatile("ldmatrix.sync.aligned.m8n8.x4.shared.b16 {%0,%1,%2,%3},[%4];" \
        : "=r"((d)[0]), "=r"((d)[1]), "=r"((d)[2]), "=r"((d)[3]) : "r"(addr))
__device__ __forceinline__ void mma_f16(float* d, const uint32_t* a, uint32_t b0, uint32_t b1) {
    asm volatile(
        "mma.sync.aligned.m16n8k16.row.col.f32.f16.f16.f32 "
        "{%0,%1,%2,%3},{%4,%5,%6,%7},{%8,%9},{%0,%1,%2,%3};"
        : "+f"(d[0]), "+f"(d[1]), "+f"(d[2]), "+f"(d[3])
        : "r"(a[0]), "r"(a[1]), "r"(a[2]), "r"(a[3]), "r"(b0), "r"(b1));
}

// ---- device scratch ----
__device__ float g_M[Am*Cch*3];
__device__ float g_bias1[Cch];
__device__ __align__(128) __half g_wH[2*2*(size_t)G4*KPS];     // input weights [dir*2+plane][g][k]
__device__ __align__(128) __half g_wHH[2*2*(size_t)G4*Hm];     // recurrent [dir][pl][512][128]
__device__ float g_fcf[Tm*Hm];
__device__ float g_fcb[Tm*Hm];
__device__ float g_cbias[Tm];
__device__ __align__(128) __half g_featH[2*(size_t)Nt*KPS];    // [plane][n][k]
__device__ float g_gates[2][(size_t)Nt*G4];
__device__ float g_emisD[2][(size_t)Nt*Tm];                    // per-dir emission partials

// ======================= prep kernels =======================
__global__ void prep_tables(const float* __restrict__ emb,
                            const float* __restrict__ conv_w,
                            const float* __restrict__ conv_b,
                            const float* __restrict__ g1,
                            const float* __restrict__ b1,
                            const float* __restrict__ m1,
                            const float* __restrict__ v1)
{
    int i = blockIdx.x*blockDim.x + threadIdx.x;
    if (i < Am*Cch*3) {
        int k = i % 3;
        int c = (i/3) % Cch;
        int a = i / (3*Cch);
        float s = 0.f;
        for (int e = 0; e < Em; e++)
            s += emb[a*Em + e] * conv_w[(c*Em + e)*3 + k];
        float sc = g1[c] * rsqrtf(v1[c] + 1e-5f);
        g_M[i] = s * sc;
    } else if (i < Am*Cch*3 + Cch) {
        int c = i - Am*Cch*3;
        float sc = g1[c] * rsqrtf(v1[c] + 1e-5f);
        g_bias1[c] = (conv_b[c] - m1[c]) * sc + b1[c];
    }
}

__global__ void prep_pack7(const float* __restrict__ wihf, const float* __restrict__ whhf,
                           const float* __restrict__ wihb, const float* __restrict__ whhb)
{
    int stride = gridDim.x * blockDim.x;
    int t0 = blockIdx.x*blockDim.x + threadIdx.x;
    for (int i = t0; i < G4*KPS; i += stride) {
        int g = i / KPS, k = i % KPS;
        float vf = (k < LIN) ? wihf[g*LIN + k] : 0.f;
        float vb = (k < LIN) ? wihb[g*LIN + k] : 0.f;
        __half h, l;
        split2h(vf, h, l);
        g_wH[(size_t)(0*2+0)*G4*KPS + i] = h;
        g_wH[(size_t)(0*2+1)*G4*KPS + i] = l;
        split2h(vb, h, l);
        g_wH[(size_t)(1*2+0)*G4*KPS + i] = h;
        g_wH[(size_t)(1*2+1)*G4*KPS + i] = l;
    }
    // recurrent weights: [512][128] row-major directly
    for (int i = t0; i < G4*Hm; i += stride) {
        __half h, l;
        split2h(whhf[i], h, l);
        g_wHH[(size_t)(0*2+0)*G4*Hm + i] = h;
        g_wHH[(size_t)(0*2+1)*G4*Hm + i] = l;
        split2h(whhb[i], h, l);
        g_wHH[(size_t)(1*2+0)*G4*Hm + i] = h;
        g_wHH[(size_t)(1*2+1)*G4*Hm + i] = l;
    }
}

__global__ void prep_fc(const float* __restrict__ g2, const float* __restrict__ b2,
                        const float* __restrict__ m2, const float* __restrict__ v2,
                        const float* __restrict__ fcw, const float* __restrict__ fcbias)
{
    int t = threadIdx.x;
    if (t < Hm) {
        float s2a = g2[t]       * rsqrtf(v2[t]       + 1e-5f);
        float s2b = g2[Hm + t]  * rsqrtf(v2[Hm + t]  + 1e-5f);
        for (int tt = 0; tt < Tm; tt++) {
            g_fcf[tt*Hm + t] = fcw[tt*2*Hm + t]      * s2a;
            g_fcb[tt*Hm + t] = fcw[tt*2*Hm + Hm + t] * s2b;
        }
    }
    if (t < Tm) {
        float s = fcbias[t];
        for (int j = 0; j < 2*Hm; j++) {
            float s2 = g2[j] * rsqrtf(v2[j] + 1e-5f);
            s += (b2[j] - m2[j]*s2) * fcw[t*2*Hm + j];
        }
        g_cbias[t] = s;
    }
}

// ======================= fused featurize -> fp16 hi/lo planes =======================
__global__ __launch_bounds__(128) void featfuse(const int* __restrict__ x)
{
    int n = blockIdx.x*128 + threadIdx.x;
    if (n >= Nt) return;
    int sym[Wm];
#pragma unroll
    for (int w = 0; w < Wm; w++) sym[w] = x[n*Wm + w];

    uint4* dh = (uint4*)(g_featH + (size_t)n*KPS);
    uint4* dl = (uint4*)(g_featH + (size_t)Nt*KPS + (size_t)n*KPS);

#pragma unroll
    for (int g = 0; g < 5; g++) {
        __align__(16) __half th[40];
        __align__(16) __half tl[40];
#pragma unroll
        for (int cc = 0; cc < 8; cc++) {
            int c = g*8 + cc;
            float bb = g_bias1[c];
            float y[Wm];
#pragma unroll
            for (int w = 0; w < Wm; w++) {
                float v = bb;
#pragma unroll
                for (int k = 0; k < 3; k++) {
                    int p = w + k - 1;
                    if (p >= 0 && p < Wm)
                        v += g_M[sym[p]*(Cch*3) + c*3 + k];
                }
                y[w] = fmaxf(v, 0.f);
            }
#pragma unroll
            for (int w = 0; w < Wm; w++) {
                float p = y[w];
                if (w > 0)      p = fmaxf(p, y[w-1]);
                if (w < Wm-1)   p = fmaxf(p, y[w+1]);
                __half h, l;
                split2h(p, h, l);
                th[cc*Wm + w] = h;
                tl[cc*Wm + w] = l;
            }
        }
        const uint4* sh = (const uint4*)th;
        const uint4* sl = (const uint4*)tl;
#pragma unroll
        for (int i = 0; i < 5; i++) {
            dh[g*5 + i] = sh[i];
            dl[g*5 + i] = sl[i];
        }
    }
    uint4 z = make_uint4(0, 0, 0, 0);
#pragma unroll
    for (int i = 25; i < 28; i++) { dh[i] = z; dl[i] = z; }
}

// ======================= input GEMM (unchanged) =======================
__global__ __launch_bounds__(256, 2) void gemm_f16s(const float* __restrict__ bias_f,
                                                    const float* __restrict__ bias_b)
{
    extern __shared__ __align__(16) char dynsm[];
    uint32_t sbase = smem_u32(dynsm);

    int dir = blockIdx.x >> 2;
    int n0  = (blockIdx.x & 3) * 128;
    int m0  = blockIdx.y * 128;
    const float* __restrict__ bias = dir ? bias_b : bias_f;
    float* __restrict__ Co = g_gates[dir];

    int t = threadIdx.x, lane = t & 31, w = t >> 5;
    int wm = w & 3, wn = w >> 2;
    int gi = lane >> 2, li = lane & 3;

    uint32_t aB[2][2], bB[2][2];
#pragma unroll
    for (int b = 0; b < 2; b++)
#pragma unroll
        for (int p = 0; p < 2; p++) {
            aB[b][p] = sbase + (uint32_t)((b*2 + p) * 8192);
            bB[b][p] = sbase + 32768u + (uint32_t)((b*2 + p) * 8192);
        }

    float acc[2][8][4];
#pragma unroll
    for (int mt = 0; mt < 2; mt++)
#pragma unroll
        for (int nt = 0; nt < 8; nt++)
#pragma unroll
            for (int q = 0; q < 4; q++) acc[mt][nt][q] = 0.f;

    int lrow = t >> 2;
    int lq   = t & 3;

    auto load_chunk = [&](int kc, int buf) {
        size_t go = (size_t)kc*32 + lq*8;
#pragma unroll
        for (int rr = 0; rr < 2; rr++) {
            int row = lrow + rr*64;
            uint32_t so = (uint32_t)(row*64 + ((lq ^ ((row >> 1) & 3)) << 4));
#pragma unroll
            for (int pl = 0; pl < 2; pl++) {
                cpasync16(aB[buf][pl] + so,
                          g_featH + ((size_t)pl*Nt + m0 + row)*KPS + go);
                cpasync16(bB[buf][pl] + so,
                          g_wH + ((size_t)(dir*2 + pl)*G4 + n0 + row)*KPS + go);
            }
        }
        cpcommit();
    };

    load_chunk(0, 0);

    int r15 = lane & 15;
    int qhi = lane >> 4;

    for (int c = 0; c < NCH; c++) {
        int buf = c & 1;
        if (c + 1 < NCH) {
            load_chunk(c + 1, buf ^ 1);
            asm volatile("cp.async.wait_group 1;");
        } else {
            asm volatile("cp.async.wait_group 0;");
        }
        __syncthreads();

#pragma unroll
        for (int kg = 0; kg < 2; kg++) {
            int qb = kg*2 + qhi;
            uint32_t bh[4][4], bl[4][4];
#pragma unroll
            for (int np = 0; np < 4; np++) {
                int row = wn*64 + np*16 + r15;
                uint32_t off = (uint32_t)(row*64 + ((qb ^ ((row >> 1) & 3)) << 4));
                LDSM4(bh[np], bB[buf][0] + off);
                LDSM4(bl[np], bB[buf][1] + off);
            }
            uint32_t ah0[4], ah1[4], al0[4], al1[4];
            {
                int row = wm*32 + r15;
                uint32_t off = (uint32_t)(row*64 + ((qb ^ ((row >> 1) & 3)) << 4));
                LDSM4(ah0, aB[buf][0] + off);
                LDSM4(al0, aB[buf][1] + off);
                row += 16;
                off = (uint32_t)(row*64 + ((qb ^ ((row >> 1) & 3)) << 4));
                LDSM4(ah1, aB[buf][0] + off);
                LDSM4(al1, aB[buf][1] + off);
            }
#pragma unroll
            for (int nt = 0; nt < 8; nt++) {
                uint32_t b0h = bh[nt >> 1][nt & 1];
                uint32_t b1h = bh[nt >> 1][2 + (nt & 1)];
                uint32_t b0l = bl[nt >> 1][nt & 1];
                uint32_t b1l = bl[nt >> 1][2 + (nt & 1)];
                mma_f16(acc[0][nt], ah0, b0h, b1h);
                mma_f16(acc[1][nt], ah1, b0h, b1h);
                mma_f16(acc[0][nt], al0, b0h, b1h);
                mma_f16(acc[1][nt], al1, b0h, b1h);
                mma_f16(acc[0][nt], ah0, b0l, b1l);
                mma_f16(acc[1][nt], ah1, b0l, b1l);
            }
        }
        __syncthreads();
    }

#pragma unroll
    for (int mt = 0; mt < 2; mt++) {
        size_t r0 = (size_t)(m0 + wm*32 + mt*16 + gi);
#pragma unroll
        for (int nt = 0; nt < 8; nt++) {
            int col = n0 + wn*64 + nt*8 + 2*li;
            float b0 = bias[col], b1 = bias[col + 1];
            float2 v;
            v.x = acc[mt][nt][0] + b0; v.y = acc[mt][nt][1] + b1;
            *(float2*)(Co + r0*G4 + col) = v;
            v.x = acc[mt][nt][2] + b0; v.y = acc[mt][nt][3] + b1;
            *(float2*)(Co + (r0 + 8)*G4 + col) = v;
        }
    }
}

// ======================= tensor-core LSTM with fused emission =======================
// Block = 64 batch rows x 1 dir; 256 threads. h stays in smem; instead of writing
// g_h, the epilogue folds h into per-dir emission partials (deterministic warp-
// staged reduction, no atomics). Dyn smem: W 131072 + h 32768 + c 33792 + e 6144.
#define LTC_WOFF 0
#define LTC_HOFF 131072
#define LTC_COFF 163840
#define LTC_EOFF 197632
#define LTC_SMEM 203776
__global__ __launch_bounds__(256, 1) void lstm_tc()
{
    extern __shared__ __align__(16) char dynsm[];
    uint32_t sb = smem_u32(dynsm);
    float* cs = (float*)(dynsm + LTC_COFF);
    float* ep = (float*)(dynsm + LTC_EOFF);   // [8][64][3]

    int t = threadIdx.x, lane = t & 31, w = t >> 5;
    int gi = lane >> 2, li = lane & 3;
    int r15 = lane & 15, qhi = lane >> 4;
    int dir = blockIdx.x & 1;
    int rb0 = (blockIdx.x >> 1) * 64;
    const float* __restrict__ gates = g_gates[dir];
    float* __restrict__ emisD = g_emisD[dir];
    const __half* __restrict__ Wg = g_wHH + (size_t)dir*2*G4*Hm;
    const float* __restrict__ fcv = dir ? g_fcb : g_fcf;

    // per-thread FC coefficients: j = w*16 + jt*8 + 2*li + cc
    float fcr[Tm][4];
#pragma unroll
    for (int tt = 0; tt < Tm; tt++)
#pragma unroll
        for (int jt = 0; jt < 2; jt++)
#pragma unroll
            for (int cc = 0; cc < 2; cc++)
                fcr[tt][jt*2+cc] = fcv[tt*Hm + w*16 + jt*8 + 2*li + cc];

    // init h smem (2 planes x 64 x 256B) and c smem to zero
    for (int i = t; i < 32768/4; i += 256) ((uint32_t*)(dynsm + LTC_HOFF))[i] = 0u;
    for (int i = t; i < 33792/4; i += 256) ((uint32_t*)(dynsm + LTC_COFF))[i] = 0u;

    auto load_quarter = [&](int qt, int s) {
        uint32_t base = sb + LTC_WOFF + (uint32_t)s*65536;
#pragma unroll
        for (int pl = 0; pl < 2; pl++) {
            const __half* src = Wg + (size_t)pl*G4*Hm + qt*32;
#pragma unroll
            for (int i = 0; i < 8; i++) {
                int idx = i*256 + t;
                int row = idx >> 2, q4 = idx & 3;
                cpasync16(base + (uint32_t)(pl*32768 + row*64 + ((q4 ^ (row & 3)) << 4)),
                          src + (size_t)row*Hm + q4*8);
            }
        }
        cpcommit();
    };

    __syncthreads();
    load_quarter(0, 0);

    int qg = 0;
    for (int st = 0; st < Lm; st++) {
        int l = dir ? (Lm-1-st) : st;

        float acc[4][8][4];
#pragma unroll
        for (int mt = 0; mt < 4; mt++)
#pragma unroll
            for (int nt = 0; nt < 8; nt++)
#pragma unroll
                for (int e = 0; e < 4; e++) acc[mt][nt][e] = 0.f;

        for (int q = 0; q < 4; q++) {
            int slot = qg & 1;
            bool last = (st == Lm-1) && (q == 3);
            if (!last) {
                load_quarter((q + 1) & 3, (qg + 1) & 1);
                asm volatile("cp.async.wait_group 1;");
            } else {
                asm volatile("cp.async.wait_group 0;");
            }
            __syncthreads();

            uint32_t wbase = sb + LTC_WOFF + (uint32_t)slot*65536;
#pragma unroll
            for (int kgl = 0; kgl < 2; kgl++) {
                int chB = kgl*2 + qhi;
                uint32_t bh[4][4], bl[4][4];
#pragma unroll
                for (int g = 0; g < 4; g++) {
                    int rowB = g*128 + w*16 + r15;
                    uint32_t off = (uint32_t)(rowB*64 + ((chB ^ (rowB & 3)) << 4));
                    LDSM4(bh[g], wbase + off);
                    LDSM4(bl[g], wbase + 32768u + off);
                }
                int chA = q*4 + kgl*2 + qhi;
                uint32_t af[4][4];
#pragma unroll
                for (int mt = 0; mt < 4; mt++) {
                    int row = mt*16 + r15;
                    LDSM4(af[mt], sb + LTC_HOFF +
                          (uint32_t)(row*256 + ((chA ^ (row & 15)) << 4)));
                }
#pragma unroll
                for (int mt = 0; mt < 4; mt++)
#pragma unroll
                    for (int nt = 0; nt < 8; nt++) {
                        int g = nt >> 1, jt = nt & 1;
                        mma_f16(acc[mt][nt], af[mt], bh[g][jt], bh[g][2+jt]);
                        mma_f16(acc[mt][nt], af[mt], bl[g][jt], bl[g][2+jt]);
                    }
#pragma unroll
                for (int mt = 0; mt < 4; mt++) {
                    int row = mt*16 + r15;
                    LDSM4(af[mt], sb + LTC_HOFF + 16384u +
                          (uint32_t)(row*256 + ((chA ^ (row & 15)) << 4)));
                }
#pragma unroll
                for (int mt = 0; mt < 4; mt++)
#pragma unroll
                    for (int nt = 0; nt < 8; nt++) {
                        int g = nt >> 1, jt = nt & 1;
                        mma_f16(acc[mt][nt], af[mt], bh[g][jt], bh[g][2+jt]);
                    }
            }
            __syncthreads();
            qg++;
        }

        // epilogue: activations + c/h update + emission partials
#pragma unroll
        for (int mt = 0; mt < 4; mt++) {
#pragma unroll
            for (int rsel = 0; rsel < 2; rsel++) {
                int row = mt*16 + gi + rsel*8;
                const float* gp = gates + ((size_t)(rb0 + row)*Lm + l)*G4 + w*16 + 2*li;
                float pt[Tm] = {0.f, 0.f, 0.f};
#pragma unroll
                for (int jt = 0; jt < 2; jt++) {
                    float2 vi = *(const float2*)(gp + jt*8 + 0*128);
                    float2 vf = *(const float2*)(gp + jt*8 + 1*128);
                    float2 vg = *(const float2*)(gp + jt*8 + 2*128);
                    float2 vo = *(const float2*)(gp + jt*8 + 3*128);
                    int j0 = w*16 + jt*8 + 2*li;
                    float hn2[2];
#pragma unroll
                    for (int cc = 0; cc < 2; cc++) {
                        float zi = acc[mt][0*2+jt][rsel*2+cc] + (cc ? vi.y : vi.x);
                        float zf = acc[mt][1*2+jt][rsel*2+cc] + (cc ? vf.y : vf.x);
                        float zg = acc[mt][2*2+jt][rsel*2+cc] + (cc ? vg.y : vg.x);
                        float zo = acc[mt][3*2+jt][rsel*2+cc] + (cc ? vo.y : vo.x);
                        float ig = sigf(zi), fg = sigf(zf);
                        float gg = tanhfast(zg), og = sigf(zo);
                        float cp = cs[row*132 + j0 + cc];
                        float cn = fg*cp + ig*gg;
                        cs[row*132 + j0 + cc] = cn;
                        float hn = og * tanhfast(cn);
                        hn2[cc] = hn;
#pragma unroll
                        for (int tt = 0; tt < Tm; tt++)
                            pt[tt] += fcr[tt][jt*2+cc] * hn;
                    }
                    __half h0, l0, h1, l1;
                    split2h(hn2[0], h0, l0);
                    split2h(hn2[1], h1, l1);
                    int chunk = j0 >> 3;
                    uint32_t ho = (uint32_t)(row*256 + ((chunk ^ (row & 15)) << 4) + (j0 & 7)*2);
                    *(__half2*)(dynsm + LTC_HOFF + ho) = __halves2half2(h0, h1);
                    *(__half2*)(dynsm + LTC_HOFF + 16384 + ho) = __halves2half2(l0, l1);
                }
                // reduce pt over the 4-lane li group (lanes gi*4..gi*4+3)
#pragma unroll
                for (int tt = 0; tt < Tm; tt++) {
                    pt[tt] += __shfl_xor_sync(0xffffffffu, pt[tt], 1);
                    pt[tt] += __shfl_xor_sync(0xffffffffu, pt[tt], 2);
                }
                if (li == 0) {
#pragma unroll
                    for (int tt = 0; tt < Tm; tt++)
                        ep[(w*64 + row)*3 + tt] = pt[tt];
                }
            }
        }
        __syncthreads();
        // deterministic flush: 192 threads sum 8 warp partials in fixed order
        if (t < 192) {
            int row = t / 3, tt = t % 3;
            float s = 0.f;
#pragma unroll
            for (int ww = 0; ww < 8; ww++)
                s += ep[(ww*64 + row)*3 + tt];
            emisD[((size_t)(rb0 + row)*Lm + l)*Tm + tt] = s;
        }
        __syncthreads();
    }
}

// ======================= Viterbi (combines per-dir emissions) =======================
__global__ void viterbi_kernel(const int* __restrict__ x,
                               const float* __restrict__ trans,
                               const float* __restrict__ start_t,
                               const float* __restrict__ end_t,
                               float* __restrict__ out)
{
    int b = blockIdx.x*blockDim.x + threadIdx.x;
    if (b >= Bsz) return;
    float tr[9];
#pragma unroll
    for (int i = 0; i < 9; i++) tr[i] = trans[i];
    const float* e0 = g_emisD[0] + (size_t)b*Lm*Tm;
    const float* e1 = g_emisD[1] + (size_t)b*Lm*Tm;
    float cb[3] = {g_cbias[0], g_cbias[1], g_cbias[2]};

    float em[Lm][3];
#pragma unroll 2
    for (int l = 0; l < Lm; l++)
#pragma unroll
        for (int tt = 0; tt < 3; tt++)
            em[l][tt] = e0[l*Tm + tt] + e1[l*Tm + tt] + cb[tt];

    float sc[3];
#pragma unroll
    for (int t = 0; t < 3; t++) sc[t] = start_t[t] + em[0][t];

    unsigned char hist[Lm-1][3];
    for (int l = 1; l < Lm; l++) {
        bool m = x[(b*Lm + l)*Wm + 2] > 0;
        float ns[3];
#pragma unroll
        for (int t = 0; t < 3; t++) {
            float best = sc[0] + tr[0*3 + t];
            int bp = 0;
#pragma unroll
            for (int p = 1; p < 3; p++) {
                float v = sc[p] + tr[p*3 + t];
                if (v > best) { best = v; bp = p; }
            }
            hist[l-1][t] = (unsigned char)bp;
            ns[t] = best + em[l][t];
        }
        if (m) { sc[0]=ns[0]; sc[1]=ns[1]; sc[2]=ns[2]; }
    }
#pragma unroll
    for (int t = 0; t < 3; t++) sc[t] += end_t[t];
    float best = sc[0]; int last = 0;
    if (sc[1] > best) { best = sc[1]; last = 1; }
    if (sc[2] > best) { best = sc[2]; last = 2; }
    out[b] = best;

    float* tagout = out + Bsz;
    int tag = last;
    tagout[(size_t)b*Lm + (Lm-1)] = (float)tag;
    for (int i = Lm-2; i >= 0; i--) {
        int prev = hist[i][tag];
        bool m = x[(b*Lm + i + 1)*Wm + 2] > 0;
        if (m) tag = prev;
        tagout[(size_t)b*Lm + i] = (float)tag;
    }
}

// ======================= launch =======================
extern "C" void kernel_launch(void* const* d_in, const int* in_sizes, int n_in,
                              void* d_out, int out_size)
{
    (void)in_sizes; (void)n_in; (void)out_size;
    const int*   x      = (const int*)  d_in[0];
    const float* emb    = (const float*)d_in[1];
    const float* conv_w = (const float*)d_in[2];
    const float* conv_b = (const float*)d_in[3];
    const float* bn1_g  = (const float*)d_in[4];
    const float* bn1_b  = (const float*)d_in[5];
    const float* bn1_m  = (const float*)d_in[6];
    const float* bn1_v  = (const float*)d_in[7];
    const float* w_ih_f = (const float*)d_in[8];
    const float* w_hh_f = (const float*)d_in[9];
    const float* b_f    = (const float*)d_in[10];
    const float* w_ih_b = (const float*)d_in[11];
    const float* w_hh_b = (const float*)d_in[12];
    const float* b_b    = (const float*)d_in[13];
    const float* bn2_g  = (const float*)d_in[14];
    const float* bn2_b  = (const float*)d_in[15];
    const float* bn2_m  = (const float*)d_in[16];
    const float* bn2_v  = (const float*)d_in[17];
    const float* fc_w   = (const float*)d_in[18];
    const float* fc_b   = (const float*)d_in[19];
    const float* trans  = (const float*)d_in[20];
    const float* start_t= (const float*)d_in[21];
    const float* end_t  = (const float*)d_in[22];
    float* out = (float*)d_out;

    cudaFuncSetAttribute(gemm_f16s, cudaFuncAttributeMaxDynamicSharedMemorySize, 65536);
    cudaFuncSetAttribute(lstm_tc, cudaFuncAttributeMaxDynamicSharedMemorySize, LTC_SMEM);

    prep_tables<<<(Am*Cch*3 + Cch + 255)/256, 256>>>(emb, conv_w, conv_b,
                                                     bn1_g, bn1_b, bn1_m, bn1_v);
    prep_pack7<<<512, 256>>>(w_ih_f, w_hh_f, w_ih_b, w_hh_b);
    prep_fc<<<1, 256>>>(bn2_g, bn2_b, bn2_m, bn2_v, fc_w, fc_b);

    featfuse<<<Nt/128, 128>>>(x);

    dim3 gg(8, Nt/128);
    gemm_f16s<<<gg, 256, 65536>>>(b_f, b_b);

    lstm_tc<<<128, 256, LTC_SMEM>>>();

    viterbi_kernel<<<(Bsz + 127)/128, 128>>>(x, trans, start_t, end_t, out);
}

// round 15
// speedup vs baseline: 1.7293x; 1.0584x over previous
#include <cuda_runtime.h>
#include <cuda_fp16.h>
#include <math.h>
#include <stdint.h>

// ---- problem constants ----
#define Bsz 4096
#define Lm  30
#define Wm  5
#define Am  30
#define Em  128
#define Cch 40
#define Hm  128
#define Tm  3
#define LIN 200
#define KPS 224          // padded K stride for fp16 planes (7 x 32)
#define Nt  (Bsz*Lm)     // 122880 tokens
#define G4  512          // 4*H gates
#define NCH 7            // 224/32 k-chunks

typedef unsigned long long u64;

__device__ __forceinline__ float sigf(float x) {
    return __fdividef(1.f, 1.f + __expf(-x));
}
__device__ __forceinline__ float tanhfast(float x) {
    return __fdividef(2.f, 1.f + __expf(-2.f * x)) - 1.f;
}
__device__ __forceinline__ void cpasync16(uint32_t smem, const void* gmem) {
    asm volatile("cp.async.ca.shared.global [%0],[%1],16;" :: "r"(smem), "l"(gmem));
}
__device__ __forceinline__ void cpcommit() {
    asm volatile("cp.async.commit_group;");
}
__device__ __forceinline__ uint32_t smem_u32(const void* p) {
    uint32_t a;
    asm("{ .reg .u64 t; cvta.to.shared.u64 t, %1; cvt.u32.u64 %0, t; }" : "=r"(a) : "l"(p));
    return a;
}
__device__ __forceinline__ void split2h(float v, __half& h, __half& l) {
    h = __float2half_rn(v);
    l = __float2half_rn(v - __half2float(h));
}
#define LDSM4(d, addr) \
    asm volatile("ldmatrix.sync.aligned.m8n8.x4.shared.b16 {%0,%1,%2,%3},[%4];" \
        : "=r"((d)[0]), "=r"((d)[1]), "=r"((d)[2]), "=r"((d)[3]) : "r"(addr))
__device__ __forceinline__ void mma_f16(float* d, const uint32_t* a, uint32_t b0, uint32_t b1) {
    asm volatile(
        "mma.sync.aligned.m16n8k16.row.col.f32.f16.f16.f32 "
        "{%0,%1,%2,%3},{%4,%5,%6,%7},{%8,%9},{%0,%1,%2,%3};"
        : "+f"(d[0]), "+f"(d[1]), "+f"(d[2]), "+f"(d[3])
        : "r"(a[0]), "r"(a[1]), "r"(a[2]), "r"(a[3]), "r"(b0), "r"(b1));
}

// ---- device scratch ----
__device__ float g_M[Am*Cch*3];
__device__ float g_bias1[Cch];
__device__ __align__(128) __half g_wH[2*2*(size_t)G4*KPS];     // input weights [dir*2+plane][g][k]
__device__ __align__(128) __half g_wHH[2*2*(size_t)G4*Hm];     // recurrent [dir][pl][512][128]
__device__ float g_fcf[Tm*Hm];
__device__ float g_fcb[Tm*Hm];
__device__ float g_cbias[Tm];
__device__ __align__(128) __half g_featH[2*(size_t)Nt*KPS];    // [plane][n][k]
__device__ float g_gates[2][(size_t)Nt*G4];
__device__ float g_emisD[2][(size_t)Nt*Tm];                    // per-dir emission partials

// ======================= prep kernels =======================
__global__ void prep_tables(const float* __restrict__ emb,
                            const float* __restrict__ conv_w,
                            const float* __restrict__ conv_b,
                            const float* __restrict__ g1,
                            const float* __restrict__ b1,
                            const float* __restrict__ m1,
                            const float* __restrict__ v1)
{
    int i = blockIdx.x*blockDim.x + threadIdx.x;
    if (i < Am*Cch*3) {
        int k = i % 3;
        int c = (i/3) % Cch;
        int a = i / (3*Cch);
        float s = 0.f;
        for (int e = 0; e < Em; e++)
            s += emb[a*Em + e] * conv_w[(c*Em + e)*3 + k];
        float sc = g1[c] * rsqrtf(v1[c] + 1e-5f);
        g_M[i] = s * sc;
    } else if (i < Am*Cch*3 + Cch) {
        int c = i - Am*Cch*3;
        float sc = g1[c] * rsqrtf(v1[c] + 1e-5f);
        g_bias1[c] = (conv_b[c] - m1[c]) * sc + b1[c];
    }
}

__global__ void prep_pack7(const float* __restrict__ wihf, const float* __restrict__ whhf,
                           const float* __restrict__ wihb, const float* __restrict__ whhb)
{
    int stride = gridDim.x * blockDim.x;
    int t0 = blockIdx.x*blockDim.x + threadIdx.x;
    for (int i = t0; i < G4*KPS; i += stride) {
        int g = i / KPS, k = i % KPS;
        float vf = (k < LIN) ? wihf[g*LIN + k] : 0.f;
        float vb = (k < LIN) ? wihb[g*LIN + k] : 0.f;
        __half h, l;
        split2h(vf, h, l);
        g_wH[(size_t)(0*2+0)*G4*KPS + i] = h;
        g_wH[(size_t)(0*2+1)*G4*KPS + i] = l;
        split2h(vb, h, l);
        g_wH[(size_t)(1*2+0)*G4*KPS + i] = h;
        g_wH[(size_t)(1*2+1)*G4*KPS + i] = l;
    }
    // recurrent weights: [512][128] row-major directly
    for (int i = t0; i < G4*Hm; i += stride) {
        __half h, l;
        split2h(whhf[i], h, l);
        g_wHH[(size_t)(0*2+0)*G4*Hm + i] = h;
        g_wHH[(size_t)(0*2+1)*G4*Hm + i] = l;
        split2h(whhb[i], h, l);
        g_wHH[(size_t)(1*2+0)*G4*Hm + i] = h;
        g_wHH[(size_t)(1*2+1)*G4*Hm + i] = l;
    }
}

__global__ void prep_fc(const float* __restrict__ g2, const float* __restrict__ b2,
                        const float* __restrict__ m2, const float* __restrict__ v2,
                        const float* __restrict__ fcw, const float* __restrict__ fcbias)
{
    int t = threadIdx.x;
    if (t < Hm) {
        float s2a = g2[t]       * rsqrtf(v2[t]       + 1e-5f);
        float s2b = g2[Hm + t]  * rsqrtf(v2[Hm + t]  + 1e-5f);
        for (int tt = 0; tt < Tm; tt++) {
            g_fcf[tt*Hm + t] = fcw[tt*2*Hm + t]      * s2a;
            g_fcb[tt*Hm + t] = fcw[tt*2*Hm + Hm + t] * s2b;
        }
    }
    if (t < Tm) {
        float s = fcbias[t];
        for (int j = 0; j < 2*Hm; j++) {
            float s2 = g2[j] * rsqrtf(v2[j] + 1e-5f);
            s += (b2[j] - m2[j]*s2) * fcw[t*2*Hm + j];
        }
        g_cbias[t] = s;
    }
}

// ======================= fused featurize -> fp16 hi/lo planes =======================
__global__ __launch_bounds__(128) void featfuse(const int* __restrict__ x)
{
    int n = blockIdx.x*128 + threadIdx.x;
    if (n >= Nt) return;
    int sym[Wm];
#pragma unroll
    for (int w = 0; w < Wm; w++) sym[w] = x[n*Wm + w];

    uint4* dh = (uint4*)(g_featH + (size_t)n*KPS);
    uint4* dl = (uint4*)(g_featH + (size_t)Nt*KPS + (size_t)n*KPS);

#pragma unroll
    for (int g = 0; g < 5; g++) {
        __align__(16) __half th[40];
        __align__(16) __half tl[40];
#pragma unroll
        for (int cc = 0; cc < 8; cc++) {
            int c = g*8 + cc;
            float bb = g_bias1[c];
            float y[Wm];
#pragma unroll
            for (int w = 0; w < Wm; w++) {
                float v = bb;
#pragma unroll
                for (int k = 0; k < 3; k++) {
                    int p = w + k - 1;
                    if (p >= 0 && p < Wm)
                        v += g_M[sym[p]*(Cch*3) + c*3 + k];
                }
                y[w] = fmaxf(v, 0.f);
            }
#pragma unroll
            for (int w = 0; w < Wm; w++) {
                float p = y[w];
                if (w > 0)      p = fmaxf(p, y[w-1]);
                if (w < Wm-1)   p = fmaxf(p, y[w+1]);
                __half h, l;
                split2h(p, h, l);
                th[cc*Wm + w] = h;
                tl[cc*Wm + w] = l;
            }
        }
        const uint4* sh = (const uint4*)th;
        const uint4* sl = (const uint4*)tl;
#pragma unroll
        for (int i = 0; i < 5; i++) {
            dh[g*5 + i] = sh[i];
            dl[g*5 + i] = sl[i];
        }
    }
    uint4 z = make_uint4(0, 0, 0, 0);
#pragma unroll
    for (int i = 25; i < 28; i++) { dh[i] = z; dl[i] = z; }
}

// ======================= input GEMM (unchanged) =======================
__global__ __launch_bounds__(256, 2) void gemm_f16s(const float* __restrict__ bias_f,
                                                    const float* __restrict__ bias_b)
{
    extern __shared__ __align__(16) char dynsm[];
    uint32_t sbase = smem_u32(dynsm);

    int dir = blockIdx.x >> 2;
    int n0  = (blockIdx.x & 3) * 128;
    int m0  = blockIdx.y * 128;
    const float* __restrict__ bias = dir ? bias_b : bias_f;
    float* __restrict__ Co = g_gates[dir];

    int t = threadIdx.x, lane = t & 31, w = t >> 5;
    int wm = w & 3, wn = w >> 2;
    int gi = lane >> 2, li = lane & 3;

    uint32_t aB[2][2], bB[2][2];
#pragma unroll
    for (int b = 0; b < 2; b++)
#pragma unroll
        for (int p = 0; p < 2; p++) {
            aB[b][p] = sbase + (uint32_t)((b*2 + p) * 8192);
            bB[b][p] = sbase + 32768u + (uint32_t)((b*2 + p) * 8192);
        }

    float acc[2][8][4];
#pragma unroll
    for (int mt = 0; mt < 2; mt++)
#pragma unroll
        for (int nt = 0; nt < 8; nt++)
#pragma unroll
            for (int q = 0; q < 4; q++) acc[mt][nt][q] = 0.f;

    int lrow = t >> 2;
    int lq   = t & 3;

    auto load_chunk = [&](int kc, int buf) {
        size_t go = (size_t)kc*32 + lq*8;
#pragma unroll
        for (int rr = 0; rr < 2; rr++) {
            int row = lrow + rr*64;
            uint32_t so = (uint32_t)(row*64 + ((lq ^ ((row >> 1) & 3)) << 4));
#pragma unroll
            for (int pl = 0; pl < 2; pl++) {
                cpasync16(aB[buf][pl] + so,
                          g_featH + ((size_t)pl*Nt + m0 + row)*KPS + go);
                cpasync16(bB[buf][pl] + so,
                          g_wH + ((size_t)(dir*2 + pl)*G4 + n0 + row)*KPS + go);
            }
        }
        cpcommit();
    };

    load_chunk(0, 0);

    int r15 = lane & 15;
    int qhi = lane >> 4;

    for (int c = 0; c < NCH; c++) {
        int buf = c & 1;
        if (c + 1 < NCH) {
            load_chunk(c + 1, buf ^ 1);
            asm volatile("cp.async.wait_group 1;");
        } else {
            asm volatile("cp.async.wait_group 0;");
        }
        __syncthreads();

#pragma unroll
        for (int kg = 0; kg < 2; kg++) {
            int qb = kg*2 + qhi;
            uint32_t bh[4][4], bl[4][4];
#pragma unroll
            for (int np = 0; np < 4; np++) {
                int row = wn*64 + np*16 + r15;
                uint32_t off = (uint32_t)(row*64 + ((qb ^ ((row >> 1) & 3)) << 4));
                LDSM4(bh[np], bB[buf][0] + off);
                LDSM4(bl[np], bB[buf][1] + off);
            }
            uint32_t ah0[4], ah1[4], al0[4], al1[4];
            {
                int row = wm*32 + r15;
                uint32_t off = (uint32_t)(row*64 + ((qb ^ ((row >> 1) & 3)) << 4));
                LDSM4(ah0, aB[buf][0] + off);
                LDSM4(al0, aB[buf][1] + off);
                row += 16;
                off = (uint32_t)(row*64 + ((qb ^ ((row >> 1) & 3)) << 4));
                LDSM4(ah1, aB[buf][0] + off);
                LDSM4(al1, aB[buf][1] + off);
            }
#pragma unroll
            for (int nt = 0; nt < 8; nt++) {
                uint32_t b0h = bh[nt >> 1][nt & 1];
                uint32_t b1h = bh[nt >> 1][2 + (nt & 1)];
                uint32_t b0l = bl[nt >> 1][nt & 1];
                uint32_t b1l = bl[nt >> 1][2 + (nt & 1)];
                mma_f16(acc[0][nt], ah0, b0h, b1h);
                mma_f16(acc[1][nt], ah1, b0h, b1h);
                mma_f16(acc[0][nt], al0, b0h, b1h);
                mma_f16(acc[1][nt], al1, b0h, b1h);
                mma_f16(acc[0][nt], ah0, b0l, b1l);
                mma_f16(acc[1][nt], ah1, b0l, b1l);
            }
        }
        __syncthreads();
    }

#pragma unroll
    for (int mt = 0; mt < 2; mt++) {
        size_t r0 = (size_t)(m0 + wm*32 + mt*16 + gi);
#pragma unroll
        for (int nt = 0; nt < 8; nt++) {
            int col = n0 + wn*64 + nt*8 + 2*li;
            float b0 = bias[col], b1 = bias[col + 1];
            float2 v;
            v.x = acc[mt][nt][0] + b0; v.y = acc[mt][nt][1] + b1;
            *(float2*)(Co + r0*G4 + col) = v;
            v.x = acc[mt][nt][2] + b0; v.y = acc[mt][nt][3] + b1;
            *(float2*)(Co + (r0 + 8)*G4 + col) = v;
        }
    }
}

// ======================= tensor-core LSTM, W_hi resident, c in regs =======================
// Block = 64 batch rows x 1 dir; 256 threads. W_hi (128KB) loaded once; W_lo
// streamed per k-quarter through one 32KB slot. c state in registers.
// Smem: WHI 131072 + WLO 32768 + h 32768 + e 6144 = 202752.
#define LTC_WHI  0
#define LTC_WLO  131072
#define LTC_HOFF 163840
#define LTC_EOFF 196608
#define LTC_SMEM 202752
__global__ __launch_bounds__(256, 1) void lstm_tc()
{
    extern __shared__ __align__(16) char dynsm[];
    uint32_t sb = smem_u32(dynsm);
    float* ep = (float*)(dynsm + LTC_EOFF);   // [8][64][3]

    int t = threadIdx.x, lane = t & 31, w = t >> 5;
    int gi = lane >> 2, li = lane & 3;
    int r15 = lane & 15, qhi = lane >> 4;
    int dir = blockIdx.x & 1;
    int rb0 = (blockIdx.x >> 1) * 64;
    const float* __restrict__ gates = g_gates[dir];
    float* __restrict__ emisD = g_emisD[dir];
    const __half* __restrict__ WgHi = g_wHH + (size_t)dir*2*G4*Hm;
    const __half* __restrict__ WgLo = WgHi + (size_t)G4*Hm;
    const float* __restrict__ fcv = dir ? g_fcb : g_fcf;

    float fcr[Tm][4];
#pragma unroll
    for (int tt = 0; tt < Tm; tt++)
#pragma unroll
        for (int jt = 0; jt < 2; jt++)
#pragma unroll
            for (int cc = 0; cc < 2; cc++)
                fcr[tt][jt*2+cc] = fcv[tt*Hm + w*16 + jt*8 + 2*li + cc];

    // c state in registers: index ((mt*2+rsel)*2+jt)*2+cc
    float cst[32];
#pragma unroll
    for (int i = 0; i < 32; i++) cst[i] = 0.f;

    // zero h planes
    for (int i = t; i < 32768/4; i += 256) ((uint32_t*)(dynsm + LTC_HOFF))[i] = 0u;

    // prologue: resident W_hi (512 rows x 256B, chunk^(row&15) swizzle)
#pragma unroll 4
    for (int i = 0; i < 32; i++) {
        int idx = i*256 + t;
        int row = idx >> 4, ch = idx & 15;
        cpasync16(sb + LTC_WHI + (uint32_t)(row*256 + ((ch ^ (row & 15)) << 4)),
                  WgHi + (size_t)row*Hm + ch*8);
    }
    cpcommit();

    auto load_lo = [&](int qt) {
#pragma unroll
        for (int i = 0; i < 8; i++) {
            int idx = i*256 + t;
            int row = idx >> 2, q4 = idx & 3;
            cpasync16(sb + LTC_WLO + (uint32_t)(row*64 + ((q4 ^ (row & 3)) << 4)),
                      WgLo + (size_t)row*Hm + qt*32 + q4*8);
        }
        cpcommit();
    };

    load_lo(0);
    asm volatile("cp.async.wait_group 0;");
    __syncthreads();

    for (int st = 0; st < Lm; st++) {
        int l = dir ? (Lm-1-st) : st;

        float acc[4][8][4];
#pragma unroll
        for (int mt = 0; mt < 4; mt++)
#pragma unroll
            for (int nt = 0; nt < 8; nt++)
#pragma unroll
                for (int e = 0; e < 4; e++) acc[mt][nt][e] = 0.f;

        for (int q = 0; q < 4; q++) {
            asm volatile("cp.async.wait_group 0;");
            __syncthreads();

#pragma unroll
            for (int kgl = 0; kgl < 2; kgl++) {
                int chB = q*4 + kgl*2 + qhi;      // W_hi chunk (0..15)
                int chL = kgl*2 + qhi;            // W_lo slot chunk (0..3)
                uint32_t bh[4][4], bl[4][4];
#pragma unroll
                for (int g = 0; g < 4; g++) {
                    int rowB = g*128 + w*16 + r15;
                    LDSM4(bh[g], sb + LTC_WHI +
                          (uint32_t)(rowB*256 + ((chB ^ (rowB & 15)) << 4)));
                    LDSM4(bl[g], sb + LTC_WLO +
                          (uint32_t)(rowB*64 + ((chL ^ (rowB & 3)) << 4)));
                }
                int chA = q*4 + kgl*2 + qhi;
                uint32_t af[4][4];
#pragma unroll
                for (int mt = 0; mt < 4; mt++) {
                    int row = mt*16 + r15;
                    LDSM4(af[mt], sb + LTC_HOFF +
                          (uint32_t)(row*256 + ((chA ^ (row & 15)) << 4)));
                }
#pragma unroll
                for (int mt = 0; mt < 4; mt++)
#pragma unroll
                    for (int nt = 0; nt < 8; nt++) {
                        int g = nt >> 1, jt = nt & 1;
                        mma_f16(acc[mt][nt], af[mt], bh[g][jt], bh[g][2+jt]);
                        mma_f16(acc[mt][nt], af[mt], bl[g][jt], bl[g][2+jt]);
                    }
#pragma unroll
                for (int mt = 0; mt < 4; mt++) {
                    int row = mt*16 + r15;
                    LDSM4(af[mt], sb + LTC_HOFF + 16384u +
                          (uint32_t)(row*256 + ((chA ^ (row & 15)) << 4)));
                }
#pragma unroll
                for (int mt = 0; mt < 4; mt++)
#pragma unroll
                    for (int nt = 0; nt < 8; nt++) {
                        int g = nt >> 1, jt = nt & 1;
                        mma_f16(acc[mt][nt], af[mt], bh[g][jt], bh[g][2+jt]);
                    }
            }
            __syncthreads();
            if (!(st == Lm-1 && q == 3)) load_lo((q + 1) & 3);
        }

        // epilogue: activations + c/h update + emission partials
#pragma unroll
        for (int mt = 0; mt < 4; mt++) {
#pragma unroll
            for (int rsel = 0; rsel < 2; rsel++) {
                int row = mt*16 + gi + rsel*8;
                const float* gp = gates + ((size_t)(rb0 + row)*Lm + l)*G4 + w*16 + 2*li;
                float pt[Tm] = {0.f, 0.f, 0.f};
#pragma unroll
                for (int jt = 0; jt < 2; jt++) {
                    float2 vi = *(const float2*)(gp + jt*8 + 0*128);
                    float2 vf = *(const float2*)(gp + jt*8 + 1*128);
                    float2 vg = *(const float2*)(gp + jt*8 + 2*128);
                    float2 vo = *(const float2*)(gp + jt*8 + 3*128);
                    int j0 = w*16 + jt*8 + 2*li;
                    float hn2[2];
#pragma unroll
                    for (int cc = 0; cc < 2; cc++) {
                        int ci = ((mt*2 + rsel)*2 + jt)*2 + cc;
                        float zi = acc[mt][0*2+jt][rsel*2+cc] + (cc ? vi.y : vi.x);
                        float zf = acc[mt][1*2+jt][rsel*2+cc] + (cc ? vf.y : vf.x);
                        float zg = acc[mt][2*2+jt][rsel*2+cc] + (cc ? vg.y : vg.x);
                        float zo = acc[mt][3*2+jt][rsel*2+cc] + (cc ? vo.y : vo.x);
                        float ig = sigf(zi), fg = sigf(zf);
                        float gg = tanhfast(zg), og = sigf(zo);
                        float cn = fg*cst[ci] + ig*gg;
                        cst[ci] = cn;
                        float hn = og * tanhfast(cn);
                        hn2[cc] = hn;
#pragma unroll
                        for (int tt = 0; tt < Tm; tt++)
                            pt[tt] += fcr[tt][jt*2+cc] * hn;
                    }
                    __half h0, l0, h1, l1;
                    split2h(hn2[0], h0, l0);
                    split2h(hn2[1], h1, l1);
                    int chunk = j0 >> 3;
                    uint32_t ho = (uint32_t)(row*256 + ((chunk ^ (row & 15)) << 4) + (j0 & 7)*2);
                    *(__half2*)(dynsm + LTC_HOFF + ho) = __halves2half2(h0, h1);
                    *(__half2*)(dynsm + LTC_HOFF + 16384 + ho) = __halves2half2(l0, l1);
                }
#pragma unroll
                for (int tt = 0; tt < Tm; tt++) {
                    pt[tt] += __shfl_xor_sync(0xffffffffu, pt[tt], 1);
                    pt[tt] += __shfl_xor_sync(0xffffffffu, pt[tt], 2);
                }
                if (li == 0) {
#pragma unroll
                    for (int tt = 0; tt < Tm; tt++)
                        ep[(w*64 + row)*3 + tt] = pt[tt];
                }
            }
        }
        __syncthreads();
        if (t < 192) {
            int row = t / 3, tt = t % 3;
            float s = 0.f;
#pragma unroll
            for (int ww = 0; ww < 8; ww++)
                s += ep[(ww*64 + row)*3 + tt];
            emisD[((size_t)(rb0 + row)*Lm + l)*Tm + tt] = s;
        }
        __syncthreads();
    }
}

// ======================= Viterbi (combines per-dir emissions) =======================
__global__ void viterbi_kernel(const int* __restrict__ x,
                               const float* __restrict__ trans,
                               const float* __restrict__ start_t,
                               const float* __restrict__ end_t,
                               float* __restrict__ out)
{
    int b = blockIdx.x*blockDim.x + threadIdx.x;
    if (b >= Bsz) return;
    float tr[9];
#pragma unroll
    for (int i = 0; i < 9; i++) tr[i] = trans[i];
    const float* e0 = g_emisD[0] + (size_t)b*Lm*Tm;
    const float* e1 = g_emisD[1] + (size_t)b*Lm*Tm;
    float cb[3] = {g_cbias[0], g_cbias[1], g_cbias[2]};

    float em[Lm][3];
#pragma unroll 2
    for (int l = 0; l < Lm; l++)
#pragma unroll
        for (int tt = 0; tt < 3; tt++)
            em[l][tt] = e0[l*Tm + tt] + e1[l*Tm + tt] + cb[tt];

    float sc[3];
#pragma unroll
    for (int t = 0; t < 3; t++) sc[t] = start_t[t] + em[0][t];

    unsigned char hist[Lm-1][3];
    for (int l = 1; l < Lm; l++) {
        bool m = x[(b*Lm + l)*Wm + 2] > 0;
        float ns[3];
#pragma unroll
        for (int t = 0; t < 3; t++) {
            float best = sc[0] + tr[0*3 + t];
            int bp = 0;
#pragma unroll
            for (int p = 1; p < 3; p++) {
                float v = sc[p] + tr[p*3 + t];
                if (v > best) { best = v; bp = p; }
            }
            hist[l-1][t] = (unsigned char)bp;
            ns[t] = best + em[l][t];
        }
        if (m) { sc[0]=ns[0]; sc[1]=ns[1]; sc[2]=ns[2]; }
    }
#pragma unroll
    for (int t = 0; t < 3; t++) sc[t] += end_t[t];
    float best = sc[0]; int last = 0;
    if (sc[1] > best) { best = sc[1]; last = 1; }
    if (sc[2] > best) { best = sc[2]; last = 2; }
    out[b] = best;

    float* tagout = out + Bsz;
    int tag = last;
    tagout[(size_t)b*Lm + (Lm-1)] = (float)tag;
    for (int i = Lm-2; i >= 0; i--) {
        int prev = hist[i][tag];
        bool m = x[(b*Lm + i + 1)*Wm + 2] > 0;
        if (m) tag = prev;
        tagout[(size_t)b*Lm + i] = (float)tag;
    }
}

// ======================= launch =======================
extern "C" void kernel_launch(void* const* d_in, const int* in_sizes, int n_in,
                              void* d_out, int out_size)
{
    (void)in_sizes; (void)n_in; (void)out_size;
    const int*   x      = (const int*)  d_in[0];
    const float* emb    = (const float*)d_in[1];
    const float* conv_w = (const float*)d_in[2];
    const float* conv_b = (const float*)d_in[3];
    const float* bn1_g  = (const float*)d_in[4];
    const float* bn1_b  = (const float*)d_in[5];
    const float* bn1_m  = (const float*)d_in[6];
    const float* bn1_v  = (const float*)d_in[7];
    const float* w_ih_f = (const float*)d_in[8];
    const float* w_hh_f = (const float*)d_in[9];
    const float* b_f    = (const float*)d_in[10];
    const float* w_ih_b = (const float*)d_in[11];
    const float* w_hh_b = (const float*)d_in[12];
    const float* b_b    = (const float*)d_in[13];
    const float* bn2_g  = (const float*)d_in[14];
    const float* bn2_b  = (const float*)d_in[15];
    const float* bn2_m  = (const float*)d_in[16];
    const float* bn2_v  = (const float*)d_in[17];
    const float* fc_w   = (const float*)d_in[18];
    const float* fc_b   = (const float*)d_in[19];
    const float* trans  = (const float*)d_in[20];
    const float* start_t= (const float*)d_in[21];
    const float* end_t  = (const float*)d_in[22];
    float* out = (float*)d_out;

    cudaFuncSetAttribute(gemm_f16s, cudaFuncAttributeMaxDynamicSharedMemorySize, 65536);
    cudaFuncSetAttribute(lstm_tc, cudaFuncAttributeMaxDynamicSharedMemorySize, LTC_SMEM);

    prep_tables<<<(Am*Cch*3 + Cch + 255)/256, 256>>>(emb, conv_w, conv_b,
                                                     bn1_g, bn1_b, bn1_m, bn1_v);
    prep_pack7<<<512, 256>>>(w_ih_f, w_hh_f, w_ih_b, w_hh_b);
    prep_fc<<<1, 256>>>(bn2_g, bn2_b, bn2_m, bn2_v, fc_w, fc_b);

    featfuse<<<Nt/128, 128>>>(x);

    dim3 gg(8, Nt/128);
    gemm_f16s<<<gg, 256, 65536>>>(b_f, b_b);

    lstm_tc<<<128, 256, LTC_SMEM>>>();

    viterbi_kernel<<<(Bsz + 127)/128, 128>>>(x, trans, start_t, end_t, out);
}

// round 17
// speedup vs baseline: 1.7628x; 1.0193x over previous
#include <cuda_runtime.h>
#include <cuda_fp16.h>
#include <math.h>
#include <stdint.h>

// ---- problem constants ----
#define Bsz 4096
#define Lm  30
#define Wm  5
#define Am  30
#define Em  128
#define Cch 40
#define Hm  128
#define Tm  3
#define LIN 200
#define KPS 224          // padded K stride for fp16 planes (7 x 32)
#define Nt  (Bsz*Lm)     // 122880 tokens
#define G4  512          // 4*H gates
#define NCH 7            // 224/32 k-chunks

typedef unsigned long long u64;

__device__ __forceinline__ float sigf(float x) {
    return __fdividef(1.f, 1.f + __expf(-x));
}
__device__ __forceinline__ float tanhfast(float x) {
    return __fdividef(2.f, 1.f + __expf(-2.f * x)) - 1.f;
}
__device__ __forceinline__ void cpasync16(uint32_t smem, const void* gmem) {
    asm volatile("cp.async.ca.shared.global [%0],[%1],16;" :: "r"(smem), "l"(gmem));
}
__device__ __forceinline__ void cpcommit() {
    asm volatile("cp.async.commit_group;");
}
__device__ __forceinline__ uint32_t smem_u32(const void* p) {
    uint32_t a;
    asm("{ .reg .u64 t; cvta.to.shared.u64 t, %1; cvt.u32.u64 %0, t; }" : "=r"(a) : "l"(p));
    return a;
}
__device__ __forceinline__ void split2h(float v, __half& h, __half& l) {
    h = __float2half_rn(v);
    l = __float2half_rn(v - __half2float(h));
}
#define LDSM4(d, addr) \
    asm volatile("ldmatrix.sync.aligned.m8n8.x4.shared.b16 {%0,%1,%2,%3},[%4];" \
        : "=r"((d)[0]), "=r"((d)[1]), "=r"((d)[2]), "=r"((d)[3]) : "r"(addr))
__device__ __forceinline__ void mma_f16(float* d, const uint32_t* a, uint32_t b0, uint32_t b1) {
    asm volatile(
        "mma.sync.aligned.m16n8k16.row.col.f32.f16.f16.f32 "
        "{%0,%1,%2,%3},{%4,%5,%6,%7},{%8,%9},{%0,%1,%2,%3};"
        : "+f"(d[0]), "+f"(d[1]), "+f"(d[2]), "+f"(d[3])
        : "r"(a[0]), "r"(a[1]), "r"(a[2]), "r"(a[3]), "r"(b0), "r"(b1));
}

// ---- device scratch ----
__device__ float g_M[Am*Cch*3];
__device__ float g_bias1[Cch];
__device__ __align__(128) __half g_wH[2*2*(size_t)G4*KPS];     // input weights [dir*2+plane][g][k]
__device__ __align__(128) __half g_wHH[2*2*(size_t)G4*Hm];     // recurrent [dir][pl][512][128]
__device__ float g_fcf[Tm*Hm];
__device__ float g_fcb[Tm*Hm];
__device__ float g_cbias[Tm];
__device__ __align__(128) __half g_featH[2*(size_t)Nt*KPS];    // [plane][n][k]
__device__ float g_gates[2][(size_t)Nt*G4];
__device__ float g_emisD[2][(size_t)Nt*Tm];                    // per-dir emission partials

// ======================= prep kernels =======================
__global__ void prep_tables(const float* __restrict__ emb,
                            const float* __restrict__ conv_w,
                            const float* __restrict__ conv_b,
                            const float* __restrict__ g1,
                            const float* __restrict__ b1,
                            const float* __restrict__ m1,
                            const float* __restrict__ v1)
{
    int i = blockIdx.x*blockDim.x + threadIdx.x;
    if (i < Am*Cch*3) {
        int k = i % 3;
        int c = (i/3) % Cch;
        int a = i / (3*Cch);
        float s = 0.f;
        for (int e = 0; e < Em; e++)
            s += emb[a*Em + e] * conv_w[(c*Em + e)*3 + k];
        float sc = g1[c] * rsqrtf(v1[c] + 1e-5f);
        g_M[i] = s * sc;
    } else if (i < Am*Cch*3 + Cch) {
        int c = i - Am*Cch*3;
        float sc = g1[c] * rsqrtf(v1[c] + 1e-5f);
        g_bias1[c] = (conv_b[c] - m1[c]) * sc + b1[c];
    }
}

__global__ void prep_pack7(const float* __restrict__ wihf, const float* __restrict__ whhf,
                           const float* __restrict__ wihb, const float* __restrict__ whhb)
{
    int stride = gridDim.x * blockDim.x;
    int t0 = blockIdx.x*blockDim.x + threadIdx.x;
    for (int i = t0; i < G4*KPS; i += stride) {
        int g = i / KPS, k = i % KPS;
        float vf = (k < LIN) ? wihf[g*LIN + k] : 0.f;
        float vb = (k < LIN) ? wihb[g*LIN + k] : 0.f;
        __half h, l;
        split2h(vf, h, l);
        g_wH[(size_t)(0*2+0)*G4*KPS + i] = h;
        g_wH[(size_t)(0*2+1)*G4*KPS + i] = l;
        split2h(vb, h, l);
        g_wH[(size_t)(1*2+0)*G4*KPS + i] = h;
        g_wH[(size_t)(1*2+1)*G4*KPS + i] = l;
    }
    // recurrent weights: [512][128] row-major directly
    for (int i = t0; i < G4*Hm; i += stride) {
        __half h, l;
        split2h(whhf[i], h, l);
        g_wHH[(size_t)(0*2+0)*G4*Hm + i] = h;
        g_wHH[(size_t)(0*2+1)*G4*Hm + i] = l;
        split2h(whhb[i], h, l);
        g_wHH[(size_t)(1*2+0)*G4*Hm + i] = h;
        g_wHH[(size_t)(1*2+1)*G4*Hm + i] = l;
    }
}

__global__ void prep_fc(const float* __restrict__ g2, const float* __restrict__ b2,
                        const float* __restrict__ m2, const float* __restrict__ v2,
                        const float* __restrict__ fcw, const float* __restrict__ fcbias)
{
    int t = threadIdx.x;
    if (t < Hm) {
        float s2a = g2[t]       * rsqrtf(v2[t]       + 1e-5f);
        float s2b = g2[Hm + t]  * rsqrtf(v2[Hm + t]  + 1e-5f);
        for (int tt = 0; tt < Tm; tt++) {
            g_fcf[tt*Hm + t] = fcw[tt*2*Hm + t]      * s2a;
            g_fcb[tt*Hm + t] = fcw[tt*2*Hm + Hm + t] * s2b;
        }
    }
    if (t < Tm) {
        float s = fcbias[t];
        for (int j = 0; j < 2*Hm; j++) {
            float s2 = g2[j] * rsqrtf(v2[j] + 1e-5f);
            s += (b2[j] - m2[j]*s2) * fcw[t*2*Hm + j];
        }
        g_cbias[t] = s;
    }
}

// ======================= fused featurize -> fp16 hi/lo planes (split by channel group) =======================
// grid (Nt/128, 5): blockIdx.y = channel group g (8 channels, 40 k-values).
__global__ __launch_bounds__(128) void featfuse(const int* __restrict__ x)
{
    int n = blockIdx.x*128 + threadIdx.x;
    int g = blockIdx.y;
    if (n >= Nt) return;
    int sym[Wm];
#pragma unroll
    for (int w = 0; w < Wm; w++) sym[w] = x[n*Wm + w];

    uint4* dh = (uint4*)(g_featH + (size_t)n*KPS);
    uint4* dl = (uint4*)(g_featH + (size_t)Nt*KPS + (size_t)n*KPS);

    __align__(16) __half th[40];
    __align__(16) __half tl[40];
#pragma unroll
    for (int cc = 0; cc < 8; cc++) {
        int c = g*8 + cc;
        float bb = g_bias1[c];
        float y[Wm];
#pragma unroll
        for (int w = 0; w < Wm; w++) {
            float v = bb;
#pragma unroll
            for (int k = 0; k < 3; k++) {
                int p = w + k - 1;
                if (p >= 0 && p < Wm)
                    v += g_M[sym[p]*(Cch*3) + c*3 + k];
            }
            y[w] = fmaxf(v, 0.f);
        }
#pragma unroll
        for (int w = 0; w < Wm; w++) {
            float p = y[w];
            if (w > 0)      p = fmaxf(p, y[w-1]);
            if (w < Wm-1)   p = fmaxf(p, y[w+1]);
            __half h, l;
            split2h(p, h, l);
            th[cc*Wm + w] = h;
            tl[cc*Wm + w] = l;
        }
    }
    const uint4* sh = (const uint4*)th;
    const uint4* sl = (const uint4*)tl;
#pragma unroll
    for (int i = 0; i < 5; i++) {
        dh[g*5 + i] = sh[i];
        dl[g*5 + i] = sl[i];
    }
    if (g == 4) {
        uint4 z = make_uint4(0, 0, 0, 0);
#pragma unroll
        for (int i = 25; i < 28; i++) { dh[i] = z; dl[i] = z; }
    }
}

// ======================= input GEMM (tail chunk kg=1 skipped: pure zero padding) =======================
__global__ __launch_bounds__(256, 2) void gemm_f16s(const float* __restrict__ bias_f,
                                                    const float* __restrict__ bias_b)
{
    extern __shared__ __align__(16) char dynsm[];
    uint32_t sbase = smem_u32(dynsm);

    int dir = blockIdx.x >> 2;
    int n0  = (blockIdx.x & 3) * 128;
    int m0  = blockIdx.y * 128;
    const float* __restrict__ bias = dir ? bias_b : bias_f;
    float* __restrict__ Co = g_gates[dir];

    int t = threadIdx.x, lane = t & 31, w = t >> 5;
    int wm = w & 3, wn = w >> 2;
    int gi = lane >> 2, li = lane & 3;

    uint32_t aB[2][2], bB[2][2];
#pragma unroll
    for (int b = 0; b < 2; b++)
#pragma unroll
        for (int p = 0; p < 2; p++) {
            aB[b][p] = sbase + (uint32_t)((b*2 + p) * 8192);
            bB[b][p] = sbase + 32768u + (uint32_t)((b*2 + p) * 8192);
        }

    float acc[2][8][4];
#pragma unroll
    for (int mt = 0; mt < 2; mt++)
#pragma unroll
        for (int nt = 0; nt < 8; nt++)
#pragma unroll
            for (int q = 0; q < 4; q++) acc[mt][nt][q] = 0.f;

    int lrow = t >> 2;
    int lq   = t & 3;

    auto load_chunk = [&](int kc, int buf) {
        size_t go = (size_t)kc*32 + lq*8;
#pragma unroll
        for (int rr = 0; rr < 2; rr++) {
            int row = lrow + rr*64;
            uint32_t so = (uint32_t)(row*64 + ((lq ^ ((row >> 1) & 3)) << 4));
#pragma unroll
            for (int pl = 0; pl < 2; pl++) {
                cpasync16(aB[buf][pl] + so,
                          g_featH + ((size_t)pl*Nt + m0 + row)*KPS + go);
                cpasync16(bB[buf][pl] + so,
                          g_wH + ((size_t)(dir*2 + pl)*G4 + n0 + row)*KPS + go);
            }
        }
        cpcommit();
    };

    load_chunk(0, 0);

    int r15 = lane & 15;
    int qhi = lane >> 4;

    for (int c = 0; c < NCH; c++) {
        int buf = c & 1;
        if (c + 1 < NCH) {
            load_chunk(c + 1, buf ^ 1);
            asm volatile("cp.async.wait_group 1;");
        } else {
            asm volatile("cp.async.wait_group 0;");
        }
        __syncthreads();

        // last chunk: k 208..223 (kg==1) is all zero padding in A and B -> skip
        int kgmax = (c == NCH-1) ? 1 : 2;
        for (int kg = 0; kg < kgmax; kg++) {
            int qb = kg*2 + qhi;
            uint32_t bh[4][4], bl[4][4];
#pragma unroll
            for (int np = 0; np < 4; np++) {
                int row = wn*64 + np*16 + r15;
                uint32_t off = (uint32_t)(row*64 + ((qb ^ ((row >> 1) & 3)) << 4));
                LDSM4(bh[np], bB[buf][0] + off);
                LDSM4(bl[np], bB[buf][1] + off);
            }
            uint32_t ah0[4], ah1[4], al0[4], al1[4];
            {
                int row = wm*32 + r15;
                uint32_t off = (uint32_t)(row*64 + ((qb ^ ((row >> 1) & 3)) << 4));
                LDSM4(ah0, aB[buf][0] + off);
                LDSM4(al0, aB[buf][1] + off);
                row += 16;
                off = (uint32_t)(row*64 + ((qb ^ ((row >> 1) & 3)) << 4));
                LDSM4(ah1, aB[buf][0] + off);
                LDSM4(al1, aB[buf][1] + off);
            }
#pragma unroll
            for (int nt = 0; nt < 8; nt++) {
                uint32_t b0h = bh[nt >> 1][nt & 1];
                uint32_t b1h = bh[nt >> 1][2 + (nt & 1)];
                uint32_t b0l = bl[nt >> 1][nt & 1];
                uint32_t b1l = bl[nt >> 1][2 + (nt & 1)];
                mma_f16(acc[0][nt], ah0, b0h, b1h);
                mma_f16(acc[1][nt], ah1, b0h, b1h);
                mma_f16(acc[0][nt], al0, b0h, b1h);
                mma_f16(acc[1][nt], al1, b0h, b1h);
                mma_f16(acc[0][nt], ah0, b0l, b1l);
                mma_f16(acc[1][nt], ah1, b0l, b1l);
            }
        }
        __syncthreads();
    }

#pragma unroll
    for (int mt = 0; mt < 2; mt++) {
        size_t r0 = (size_t)(m0 + wm*32 + mt*16 + gi);
#pragma unroll
        for (int nt = 0; nt < 8; nt++) {
            int col = n0 + wn*64 + nt*8 + 2*li;
            float b0 = bias[col], b1 = bias[col + 1];
            float2 v;
            v.x = acc[mt][nt][0] + b0; v.y = acc[mt][nt][1] + b1;
            *(float2*)(Co + r0*G4 + col) = v;
            v.x = acc[mt][nt][2] + b0; v.y = acc[mt][nt][3] + b1;
            *(float2*)(Co + (r0 + 8)*G4 + col) = v;
        }
    }
}

// ======================= tensor-core LSTM, W_hi resident, c in regs (unchanged) =======================
#define LTC_WHI  0
#define LTC_WLO  131072
#define LTC_HOFF 163840
#define LTC_EOFF 196608
#define LTC_SMEM 202752
__global__ __launch_bounds__(256, 1) void lstm_tc()
{
    extern __shared__ __align__(16) char dynsm[];
    uint32_t sb = smem_u32(dynsm);
    float* ep = (float*)(dynsm + LTC_EOFF);   // [8][64][3]

    int t = threadIdx.x, lane = t & 31, w = t >> 5;
    int gi = lane >> 2, li = lane & 3;
    int r15 = lane & 15, qhi = lane >> 4;
    int dir = blockIdx.x & 1;
    int rb0 = (blockIdx.x >> 1) * 64;
    const float* __restrict__ gates = g_gates[dir];
    float* __restrict__ emisD = g_emisD[dir];
    const __half* __restrict__ WgHi = g_wHH + (size_t)dir*2*G4*Hm;
    const __half* __restrict__ WgLo = WgHi + (size_t)G4*Hm;
    const float* __restrict__ fcv = dir ? g_fcb : g_fcf;

    float fcr[Tm][4];
#pragma unroll
    for (int tt = 0; tt < Tm; tt++)
#pragma unroll
        for (int jt = 0; jt < 2; jt++)
#pragma unroll
            for (int cc = 0; cc < 2; cc++)
                fcr[tt][jt*2+cc] = fcv[tt*Hm + w*16 + jt*8 + 2*li + cc];

    float cst[32];
#pragma unroll
    for (int i = 0; i < 32; i++) cst[i] = 0.f;

    for (int i = t; i < 32768/4; i += 256) ((uint32_t*)(dynsm + LTC_HOFF))[i] = 0u;

#pragma unroll 4
    for (int i = 0; i < 32; i++) {
        int idx = i*256 + t;
        int row = idx >> 4, ch = idx & 15;
        cpasync16(sb + LTC_WHI + (uint32_t)(row*256 + ((ch ^ (row & 15)) << 4)),
                  WgHi + (size_t)row*Hm + ch*8);
    }
    cpcommit();

    auto load_lo = [&](int qt) {
#pragma unroll
        for (int i = 0; i < 8; i++) {
            int idx = i*256 + t;
            int row = idx >> 2, q4 = idx & 3;
            cpasync16(sb + LTC_WLO + (uint32_t)(row*64 + ((q4 ^ (row & 3)) << 4)),
                      WgLo + (size_t)row*Hm + qt*32 + q4*8);
        }
        cpcommit();
    };

    load_lo(0);
    asm volatile("cp.async.wait_group 0;");
    __syncthreads();

    for (int st = 0; st < Lm; st++) {
        int l = dir ? (Lm-1-st) : st;

        float acc[4][8][4];
#pragma unroll
        for (int mt = 0; mt < 4; mt++)
#pragma unroll
            for (int nt = 0; nt < 8; nt++)
#pragma unroll
                for (int e = 0; e < 4; e++) acc[mt][nt][e] = 0.f;

        for (int q = 0; q < 4; q++) {
            asm volatile("cp.async.wait_group 0;");
            __syncthreads();

#pragma unroll
            for (int kgl = 0; kgl < 2; kgl++) {
                int chB = q*4 + kgl*2 + qhi;
                int chL = kgl*2 + qhi;
                uint32_t bh[4][4], bl[4][4];
#pragma unroll
                for (int g = 0; g < 4; g++) {
                    int rowB = g*128 + w*16 + r15;
                    LDSM4(bh[g], sb + LTC_WHI +
                          (uint32_t)(rowB*256 + ((chB ^ (rowB & 15)) << 4)));
                    LDSM4(bl[g], sb + LTC_WLO +
                          (uint32_t)(rowB*64 + ((chL ^ (rowB & 3)) << 4)));
                }
                int chA = q*4 + kgl*2 + qhi;
                uint32_t af[4][4];
#pragma unroll
                for (int mt = 0; mt < 4; mt++) {
                    int row = mt*16 + r15;
                    LDSM4(af[mt], sb + LTC_HOFF +
                          (uint32_t)(row*256 + ((chA ^ (row & 15)) << 4)));
                }
#pragma unroll
                for (int mt = 0; mt < 4; mt++)
#pragma unroll
                    for (int nt = 0; nt < 8; nt++) {
                        int g = nt >> 1, jt = nt & 1;
                        mma_f16(acc[mt][nt], af[mt], bh[g][jt], bh[g][2+jt]);
                        mma_f16(acc[mt][nt], af[mt], bl[g][jt], bl[g][2+jt]);
                    }
#pragma unroll
                for (int mt = 0; mt < 4; mt++) {
                    int row = mt*16 + r15;
                    LDSM4(af[mt], sb + LTC_HOFF + 16384u +
                          (uint32_t)(row*256 + ((chA ^ (row & 15)) << 4)));
                }
#pragma unroll
                for (int mt = 0; mt < 4; mt++)
#pragma unroll
                    for (int nt = 0; nt < 8; nt++) {
                        int g = nt >> 1, jt = nt & 1;
                        mma_f16(acc[mt][nt], af[mt], bh[g][jt], bh[g][2+jt]);
                    }
            }
            __syncthreads();
            if (!(st == Lm-1 && q == 3)) load_lo((q + 1) & 3);
        }

#pragma unroll
        for (int mt = 0; mt < 4; mt++) {
#pragma unroll
            for (int rsel = 0; rsel < 2; rsel++) {
                int row = mt*16 + gi + rsel*8;
                const float* gp = gates + ((size_t)(rb0 + row)*Lm + l)*G4 + w*16 + 2*li;
                float pt[Tm] = {0.f, 0.f, 0.f};
#pragma unroll
                for (int jt = 0; jt < 2; jt++) {
                    float2 vi = *(const float2*)(gp + jt*8 + 0*128);
                    float2 vf = *(const float2*)(gp + jt*8 + 1*128);
                    float2 vg = *(const float2*)(gp + jt*8 + 2*128);
                    float2 vo = *(const float2*)(gp + jt*8 + 3*128);
                    int j0 = w*16 + jt*8 + 2*li;
                    float hn2[2];
#pragma unroll
                    for (int cc = 0; cc < 2; cc++) {
                        int ci = ((mt*2 + rsel)*2 + jt)*2 + cc;
                        float zi = acc[mt][0*2+jt][rsel*2+cc] + (cc ? vi.y : vi.x);
                        float zf = acc[mt][1*2+jt][rsel*2+cc] + (cc ? vf.y : vf.x);
                        float zg = acc[mt][2*2+jt][rsel*2+cc] + (cc ? vg.y : vg.x);
                        float zo = acc[mt][3*2+jt][rsel*2+cc] + (cc ? vo.y : vo.x);
                        float ig = sigf(zi), fg = sigf(zf);
                        float gg = tanhfast(zg), og = sigf(zo);
                        float cn = fg*cst[ci] + ig*gg;
                        cst[ci] = cn;
                        float hn = og * tanhfast(cn);
                        hn2[cc] = hn;
#pragma unroll
                        for (int tt = 0; tt < Tm; tt++)
                            pt[tt] += fcr[tt][jt*2+cc] * hn;
                    }
                    __half h0, l0, h1, l1;
                    split2h(hn2[0], h0, l0);
                    split2h(hn2[1], h1, l1);
                    int chunk = j0 >> 3;
                    uint32_t ho = (uint32_t)(row*256 + ((chunk ^ (row & 15)) << 4) + (j0 & 7)*2);
                    *(__half2*)(dynsm + LTC_HOFF + ho) = __halves2half2(h0, h1);
                    *(__half2*)(dynsm + LTC_HOFF + 16384 + ho) = __halves2half2(l0, l1);
                }
#pragma unroll
                for (int tt = 0; tt < Tm; tt++) {
                    pt[tt] += __shfl_xor_sync(0xffffffffu, pt[tt], 1);
                    pt[tt] += __shfl_xor_sync(0xffffffffu, pt[tt], 2);
                }
                if (li == 0) {
#pragma unroll
                    for (int tt = 0; tt < Tm; tt++)
                        ep[(w*64 + row)*3 + tt] = pt[tt];
                }
            }
        }
        __syncthreads();
        if (t < 192) {
            int row = t / 3, tt = t % 3;
            float s = 0.f;
#pragma unroll
            for (int ww = 0; ww < 8; ww++)
                s += ep[(ww*64 + row)*3 + tt];
            emisD[((size_t)(rb0 + row)*Lm + l)*Tm + tt] = s;
        }
        __syncthreads();
    }
}

// ======================= Viterbi (bit-packed backpointers, no local em array) =======================
__global__ void viterbi_kernel(const int* __restrict__ x,
                               const float* __restrict__ trans,
                               const float* __restrict__ start_t,
                               const float* __restrict__ end_t,
                               float* __restrict__ out)
{
    int b = blockIdx.x*blockDim.x + threadIdx.x;
    if (b >= Bsz) return;
    float tr[9];
#pragma unroll
    for (int i = 0; i < 9; i++) tr[i] = trans[i];
    const float* e0 = g_emisD[0] + (size_t)b*Lm*Tm;
    const float* e1 = g_emisD[1] + (size_t)b*Lm*Tm;
    float cb[3] = {g_cbias[0], g_cbias[1], g_cbias[2]};

    float sc[3];
#pragma unroll
    for (int t = 0; t < 3; t++) sc[t] = start_t[t] + e0[t] + e1[t] + cb[t];

    u64 hb[3] = {0ull, 0ull, 0ull};
    uint32_t mbits = 0;
    for (int l = 1; l < Lm; l++) {
        bool m = x[(b*Lm + l)*Wm + 2] > 0;
        if (m) mbits |= (1u << l);
        float e[3];
#pragma unroll
        for (int tt = 0; tt < 3; tt++)
            e[tt] = e0[l*Tm + tt] + e1[l*Tm + tt] + cb[tt];
        float ns[3];
#pragma unroll
        for (int t = 0; t < 3; t++) {
            float best = sc[0] + tr[0*3 + t];
            int bp = 0;
            float v = sc[1] + tr[1*3 + t];
            if (v > best) { best = v; bp = 1; }
            v = sc[2] + tr[2*3 + t];
            if (v > best) { best = v; bp = 2; }
            hb[t] |= (u64)bp << (2*(l-1));
            ns[t] = best + e[t];
        }
        if (m) { sc[0]=ns[0]; sc[1]=ns[1]; sc[2]=ns[2]; }
    }
#pragma unroll
    for (int t = 0; t < 3; t++) sc[t] += end_t[t];
    float best = sc[0]; int last = 0;
    if (sc[1] > best) { best = sc[1]; last = 1; }
    if (sc[2] > best) { best = sc[2]; last = 2; }
    out[b] = best;

    float* tagout = out + Bsz;
    int tag = last;
    tagout[(size_t)b*Lm + (Lm-1)] = (float)tag;
    for (int i = Lm-2; i >= 0; i--) {
        int prev = (int)((hb[tag] >> (2*i)) & 3ull);
        if ((mbits >> (i + 1)) & 1u) tag = prev;
        tagout[(size_t)b*Lm + i] = (float)tag;
    }
}

// ======================= launch =======================
extern "C" void kernel_launch(void* const* d_in, const int* in_sizes, int n_in,
                              void* d_out, int out_size)
{
    (void)in_sizes; (void)n_in; (void)out_size;
    const int*   x      = (const int*)  d_in[0];
    const float* emb    = (const float*)d_in[1];
    const float* conv_w = (const float*)d_in[2];
    const float* conv_b = (const float*)d_in[3];
    const float* bn1_g  = (const float*)d_in[4];
    const float* bn1_b  = (const float*)d_in[5];
    const float* bn1_m  = (const float*)d_in[6];
    const float* bn1_v  = (const float*)d_in[7];
    const float* w_ih_f = (const float*)d_in[8];
    const float* w_hh_f = (const float*)d_in[9];
    const float* b_f    = (const float*)d_in[10];
    const float* w_ih_b = (const float*)d_in[11];
    const float* w_hh_b = (const float*)d_in[12];
    const float* b_b    = (const float*)d_in[13];
    const float* bn2_g  = (const float*)d_in[14];
    const float* bn2_b  = (const float*)d_in[15];
    const float* bn2_m  = (const float*)d_in[16];
    const float* bn2_v  = (const float*)d_in[17];
    const float* fc_w   = (const float*)d_in[18];
    const float* fc_b   = (const float*)d_in[19];
    const float* trans  = (const float*)d_in[20];
    const float* start_t= (const float*)d_in[21];
    const float* end_t  = (const float*)d_in[22];
    float* out = (float*)d_out;

    cudaFuncSetAttribute(gemm_f16s, cudaFuncAttributeMaxDynamicSharedMemorySize, 65536);
    cudaFuncSetAttribute(lstm_tc, cudaFuncAttributeMaxDynamicSharedMemorySize, LTC_SMEM);

    prep_tables<<<(Am*Cch*3 + Cch + 255)/256, 256>>>(emb, conv_w, conv_b,
                                                     bn1_g, bn1_b, bn1_m, bn1_v);
    prep_pack7<<<512, 256>>>(w_ih_f, w_hh_f, w_ih_b, w_hh_b);
    prep_fc<<<1, 256>>>(bn2_g, bn2_b, bn2_m, bn2_v, fc_w, fc_b);

    dim3 fg(Nt/128, 5);
    featfuse<<<fg, 128>>>(x);

    dim3 gg(8, Nt/128);
    gemm_f16s<<<gg, 256, 65536>>>(b_f, b_b);

    lstm_tc<<<128, 256, LTC_SMEM>>>();

    viterbi_kernel<<<(Bsz + 127)/128, 128>>>(x, trans, start_t, end_t, out);
}